// round 4
// baseline (speedup 1.0000x reference)
#include <cuda_runtime.h>
#include <cuda_bf16.h>
#include <cstdint>

#define N_NODES 20000
#define N_EDGES 320000

// ---------------- device scratch ------------------------------------------
__device__ float g_f [N_NODES * 256];       // f0|f1 (deg/attr/inv8 folded in)
__device__ float g_ew[N_EDGES * 256];       // per-edge MLP weights, DST-SORTED
__device__ int   g_cnt[N_NODES];
__device__ int   g_off[N_NODES + 1];
__device__ int   g_cur[N_NODES];
__device__ int   g_perm[N_EDGES];           // edge id -> sorted position
__device__ int   g_srcp[N_EDGES];           // sorted position -> src node
__device__ float4 g_eap[N_EDGES];           // sorted position -> edge_attr
__device__ __nv_bfloat16 g_W2t_h[256 * 112];
__device__ __nv_bfloat16 g_W2t_l[256 * 112];

// ---------------- constants -----------------------------------------------
#define INV8        0.125f
#define INV_SQRT10  0.3162277660168379f
#define INV10       0.1f
#define INV_SQRT3   0.5773502691896258f
#define INV_SQRT128 0.08838834764831845f
#define C_S         0.3826834323650898f
#define C_X         0.9238795325112867f

// ============================================================================
// K1: node self-interaction (unchanged)
// ============================================================================
__global__ __launch_bounds__(256) void k_node(
    const float* __restrict__ x, const float* __restrict__ attr,
    const float* __restrict__ deg,
    const float* __restrict__ Wli0, const float* __restrict__ Wli1,
    const float* __restrict__ Wlm0, const float* __restrict__ Wlm1,
    float* __restrict__ out)
{
    extern __shared__ float sm[];
    float* sWf0 = sm;
    float* sWf1 = sm + 4096;
    float* sWm0 = sm + 8192;
    float* sWm1 = sm + 12288;
    float* sx   = sm + 16384;     // 8 * 257

    int t = threadIdx.x;
    for (int i = t; i < 4096; i += 256) {
        sWf0[i] = Wli0[i]; sWf1[i] = Wli1[i];
        sWm0[i] = Wlm0[i]; sWm1[i] = Wlm1[i];
    }
    int nb = blockIdx.x * 8;
    for (int i = t; i < 8 * 256; i += 256) {
        int node = i >> 8, cc = i & 255;
        sx[node * 257 + cc] = x[(nb + node) * 256 + cc];
    }
    __syncthreads();

    int c = t;
    bool isS = (c < 64);
    int k = isS ? c : (c - 64) / 3;
    int m = isS ? 0 : (c - 64) % 3;
    int xoff = isS ? 0 : (64 + m);
    int xstr = isS ? 1 : 3;
    const float* wf = (isS ? sWf0 : sWf1) + k;
    const float* wm = (isS ? sWm0 : sWm1) + k;
    const float* xp = sx + xoff;

    float accf[8], accm[8];
#pragma unroll
    for (int i = 0; i < 8; i++) { accf[i] = 0.f; accm[i] = 0.f; }

#pragma unroll 4
    for (int u = 0; u < 64; u++) {
        float vf = wf[u * 64];
        float vm = wm[u * 64];
#pragma unroll
        for (int i = 0; i < 8; i++) {
            float xv = xp[i * 257 + u * xstr];
            accf[i] = fmaf(xv, vf, accf[i]);
            accm[i] = fmaf(xv, vm, accm[i]);
        }
    }
#pragma unroll
    for (int i = 0; i < 8; i++) {
        int n = nb + i;
        float a  = attr[n];
        float sf = INV8 * a * rsqrtf(deg[n]);
        float sc = INV8 * a * C_S;
        g_f[n * 256 + c] = accf[i] * sf;
        out[n * 256 + c] = accm[i] * sc;
    }
}

// ============================================================================
// CSR build kernels
// ============================================================================
__global__ __launch_bounds__(256) void k_zero() {
    int i = blockIdx.x * 256 + threadIdx.x;
    if (i < N_NODES) g_cnt[i] = 0;
}
__global__ __launch_bounds__(256) void k_hist(const int* __restrict__ dst) {
    int i = blockIdx.x * 256 + threadIdx.x;
    if (i < N_EDGES) atomicAdd(&g_cnt[dst[i]], 1);
}
// 1024 threads, 20 elems/thread, single block-scan round
__global__ __launch_bounds__(1024) void k_scan() {
    int t = threadIdx.x, lane = t & 31, wid = t >> 5;
    __shared__ int wsum[32];
    int base = t * 20;
    int loc[20];
    int s = 0;
#pragma unroll
    for (int j = 0; j < 20; j++) {
        int i = base + j;
        int v = (i < N_NODES) ? g_cnt[i] : 0;
        loc[j] = s; s += v;
    }
    int x = s;
#pragma unroll
    for (int d = 1; d < 32; d <<= 1) {
        int y = __shfl_up_sync(0xffffffffu, x, d);
        if (lane >= d) x += y;
    }
    if (lane == 31) wsum[wid] = x;
    __syncthreads();
    if (wid == 0) {
        int v2 = wsum[lane];
#pragma unroll
        for (int d = 1; d < 32; d <<= 1) {
            int y = __shfl_up_sync(0xffffffffu, v2, d);
            if (lane >= d) v2 += y;
        }
        wsum[lane] = v2;
    }
    __syncthreads();
    int excl = (wid ? wsum[wid - 1] : 0) + x - s;
#pragma unroll
    for (int j = 0; j < 20; j++) {
        int i = base + j;
        if (i < N_NODES) { g_off[i] = excl + loc[j]; g_cur[i] = excl + loc[j]; }
    }
    if (t == 1023) g_off[N_NODES] = excl + s;
}
// fill: also build sorted src / edge-attr arrays and perm
__global__ __launch_bounds__(256) void k_fill(
    const int* __restrict__ dst, const int* __restrict__ src,
    const float* __restrict__ eattr)
{
    int i = blockIdx.x * 256 + threadIdx.x;
    if (i < N_EDGES) {
        int d = dst[i];
        int p = atomicAdd(&g_cur[d], 1);
        g_perm[i] = p;
        g_srcp[p] = src[i];
        g_eap[p]  = ((const float4*)eattr)[i];
    }
}

// ============================================================================
// K-prep: split W2^T into bf16 hi/lo, [n=256][k=112]
// ============================================================================
__global__ __launch_bounds__(256) void k_prep(const float* __restrict__ W2) {
    int idx = blockIdx.x * 256 + threadIdx.x;
    if (idx >= 256 * 112) return;
    int n = idx / 112, k = idx - n * 112;
    float v = (k < 100) ? W2[k * 256 + n] : 0.0f;
    __nv_bfloat16 h = __float2bfloat16(v);
    __nv_bfloat16 l = __float2bfloat16(v - __bfloat162float(h));
    g_W2t_h[idx] = h;
    g_W2t_l[idx] = l;
}

// ============================================================================
// K2 (HMMA): ew rows scattered to dst-sorted positions via g_perm
// ============================================================================
#define RSTR 120
#define OFF_W1 0
#define OFF_AH 4096
#define OFF_AL 34816
#define OFF_BH 65536
#define OFF_BL 126976
#define MLP_SMEM 188416

__device__ __forceinline__ void mma16816(
    float& c0, float& c1, float& c2, float& c3,
    uint32_t a0, uint32_t a1, uint32_t a2, uint32_t a3,
    uint32_t b0, uint32_t b1)
{
    asm volatile(
        "mma.sync.aligned.m16n8k16.row.col.f32.bf16.bf16.f32 "
        "{%0,%1,%2,%3}, {%4,%5,%6,%7}, {%8,%9}, {%0,%1,%2,%3};"
        : "+f"(c0), "+f"(c1), "+f"(c2), "+f"(c3)
        : "r"(a0), "r"(a1), "r"(a2), "r"(a3), "r"(b0), "r"(b1));
}

__device__ __forceinline__ uint32_t pack_bf2(__nv_bfloat16 a, __nv_bfloat16 b) {
    return (uint32_t)__bfloat16_as_ushort(a) |
           ((uint32_t)__bfloat16_as_ushort(b) << 16);
}

__global__ __launch_bounds__(256, 1) void k_mlp_mma(
    const float* __restrict__ elen, const float* __restrict__ W1)
{
    extern __shared__ char smc[];
    float* sW1 = (float*)(smc + OFF_W1);
    __nv_bfloat16* sAh = (__nv_bfloat16*)(smc + OFF_AH);
    __nv_bfloat16* sAl = (__nv_bfloat16*)(smc + OFF_AL);
    __nv_bfloat16* sBh = (__nv_bfloat16*)(smc + OFF_BH);
    __nv_bfloat16* sBl = (__nv_bfloat16*)(smc + OFF_BL);

    int t = threadIdx.x, wid = t >> 5, lane = t & 31;
    int e0 = blockIdx.x * 128;

    for (int i = t; i < 1000; i += 256) sW1[i] = W1[i];
    {
        int n = t;
        const uint4* srcH = (const uint4*)(g_W2t_h + n * 112);
        const uint4* srcL = (const uint4*)(g_W2t_l + n * 112);
        uint4* dstH = (uint4*)(sBh + n * RSTR);
        uint4* dstL = (uint4*)(sBl + n * RSTR);
#pragma unroll
        for (int j = 0; j < 14; j++) { dstH[j] = srcH[j]; dstL[j] = srcL[j]; }
    }

    {
        int e  = t & 127;
        int kh = t >> 7;
        float el[10];
        const float* ep = elen + (e0 + e) * 10;
#pragma unroll
        for (int b = 0; b < 10; b++) el[b] = __ldg(ep + b);
        int kbase = 56 * kh;
#pragma unroll 1
        for (int kk = 0; kk < 56; kk += 2) {
            float h2[2];
#pragma unroll
            for (int jj = 0; jj < 2; jj++) {
                int k = kbase + kk + jj;
                float hv = 0.f;
                if (k < 100) {
                    float acc = 0.f;
#pragma unroll
                    for (int b = 0; b < 10; b++)
                        acc = fmaf(el[b], sW1[b * 100 + k], acc);
                    float xx = acc * INV_SQRT10;
                    hv = xx / (1.0f + __expf(-xx));
                }
                h2[jj] = hv;
            }
            __nv_bfloat16 h0 = __float2bfloat16(h2[0]);
            __nv_bfloat16 h1 = __float2bfloat16(h2[1]);
            __nv_bfloat16 l0 = __float2bfloat16(h2[0] - __bfloat162float(h0));
            __nv_bfloat16 l1 = __float2bfloat16(h2[1] - __bfloat162float(h1));
            int off = e * RSTR + kbase + kk;
            *(uint32_t*)(sAh + off) = pack_bf2(h0, h1);
            *(uint32_t*)(sAl + off) = pack_bf2(l0, l1);
        }
    }
    __syncthreads();

    int wm = wid & 3;
    int wn = wid >> 2;
    int rowA = 32 * wm + (lane >> 2);
    int kA   = (lane & 3) * 2;
    int rowB = 128 * wn + (lane >> 2);

    float acc[2][16][4];
#pragma unroll
    for (int mt = 0; mt < 2; mt++)
#pragma unroll
        for (int nt = 0; nt < 16; nt++)
#pragma unroll
            for (int j = 0; j < 4; j++) acc[mt][nt][j] = 0.f;

    const __nv_bfloat16* Aptr[3] = { sAh, sAh, sAl };
    const __nv_bfloat16* Bptr[3] = { sBh, sBl, sBh };

#pragma unroll 1
    for (int ks = 0; ks < 7; ks++) {
        int k0 = ks * 16 + kA;
#pragma unroll
        for (int p = 0; p < 3; p++) {
            const __nv_bfloat16* A = Aptr[p] + rowA * RSTR + k0;
            const __nv_bfloat16* B = Bptr[p] + rowB * RSTR + k0;
            uint32_t a[2][4];
#pragma unroll
            for (int mt = 0; mt < 2; mt++) {
                const __nv_bfloat16* Am = A + mt * 16 * RSTR;
                a[mt][0] = *(const uint32_t*)(Am);
                a[mt][1] = *(const uint32_t*)(Am + 8 * RSTR);
                a[mt][2] = *(const uint32_t*)(Am + 8);
                a[mt][3] = *(const uint32_t*)(Am + 8 * RSTR + 8);
            }
#pragma unroll
            for (int nt = 0; nt < 16; nt++) {
                const __nv_bfloat16* Bn = B + nt * 8 * RSTR;
                uint32_t b0 = *(const uint32_t*)(Bn);
                uint32_t b1 = *(const uint32_t*)(Bn + 8);
#pragma unroll
                for (int mt = 0; mt < 2; mt++)
                    mma16816(acc[mt][nt][0], acc[mt][nt][1],
                             acc[mt][nt][2], acc[mt][nt][3],
                             a[mt][0], a[mt][1], a[mt][2], a[mt][3], b0, b1);
            }
        }
    }

    // epilogue: scatter rows to dst-sorted positions (streaming stores)
    int erow = e0 + 32 * wm + (lane >> 2);
    int col  = 128 * wn + (lane & 3) * 2;
    int prow[4];
#pragma unroll
    for (int j = 0; j < 4; j++) prow[j] = __ldg(&g_perm[erow + 8 * j]);
#pragma unroll
    for (int mt = 0; mt < 2; mt++) {
        float* r0 = g_ew + (size_t)prow[2 * mt]     * 256 + col;
        float* r1 = g_ew + (size_t)prow[2 * mt + 1] * 256 + col;
#pragma unroll
        for (int nt = 0; nt < 16; nt++) {
            int c = nt * 8;
            __stcs((float2*)(r0 + c),
                   make_float2(acc[mt][nt][0] * INV10, acc[mt][nt][1] * INV10));
            __stcs((float2*)(r1 + c),
                   make_float2(acc[mt][nt][2] * INV10, acc[mt][nt][3] * INV10));
        }
    }
}

// ============================================================================
// K3: pull kernel — streams dst-sorted arrays, no indirection but g_f gather
// ============================================================================
__global__ __launch_bounds__(256) void k_pull(
    const float* __restrict__ attr, const float* __restrict__ deg,
    const float* __restrict__ Wlo0, const float* __restrict__ Wlo1,
    float* __restrict__ out)
{
    extern __shared__ float sm[];
    float* sW0  = sm;
    float* sW1  = sm + 8192;
    float* s_sv = sm + 16384;

    int t = threadIdx.x;
    for (int i = t; i < 8192; i += 256) { sW0[i] = Wlo0[i]; sW1[i] = Wlo1[i]; }
    __syncthreads();

    int w = t >> 5, lane = t & 31;
    int n = blockIdx.x * 8 + w;
    int beg = g_off[n], end = g_off[n + 1];

    float sa0 = 0.f, sa1 = 0.f, sb0 = 0.f, sb1 = 0.f;
    float va0x=0.f,va0y=0.f,va0z=0.f, va1x=0.f,va1y=0.f,va1z=0.f;
    float vb0x=0.f,vb0y=0.f,vb0z=0.f, vb1x=0.f,vb1y=0.f,vb1z=0.f;

    int src_n = (beg < end) ? __ldg(&g_srcp[beg]) : 0;

    for (int p = beg; p < end; p++) {
        int src = src_n;
        if (p + 1 < end) src_n = __ldg(&g_srcp[p + 1]);
        float4 ea = __ldg(&g_eap[p]);
        float y0 = ea.x, y1x = ea.y, y1y = ea.z, y1z = ea.w;
        const float* fp = g_f  + src * 256;
        const float* wp = g_ew + (size_t)p * 256;

        float2 G0 = *(const float2*)(fp + 2 * lane);
        float2 Ga = *(const float2*)(fp + 64 + 6 * lane);
        float2 Gb = *(const float2*)(fp + 64 + 6 * lane + 2);
        float2 Gc = *(const float2*)(fp + 64 + 6 * lane + 4);
        float2 WA = __ldcs((const float2*)(wp + 2 * lane));
        float2 WB = __ldcs((const float2*)(wp + 64 + 2 * lane));
        float2 WC = __ldcs((const float2*)(wp + 128 + 2 * lane));
        float2 WD = __ldcs((const float2*)(wp + 192 + 2 * lane));

        {
            float g1x = Ga.x, g1y = Ga.y, g1z = Gb.x;
            float d3 = fmaf(g1x, y1x, fmaf(g1y, y1y, g1z * y1z));
            sa0 = fmaf(WA.x * G0.x, y0, sa0);
            sb0 = fmaf(WB.x, d3, sb0);
            float cg = WC.x * G0.x;
            va0x = fmaf(cg, y1x, va0x); va0y = fmaf(cg, y1y, va0y); va0z = fmaf(cg, y1z, va0z);
            float dg = WD.x * y0;
            vb0x = fmaf(dg, g1x, vb0x); vb0y = fmaf(dg, g1y, vb0y); vb0z = fmaf(dg, g1z, vb0z);
        }
        {
            float g1x = Gb.y, g1y = Gc.x, g1z = Gc.y;
            float d3 = fmaf(g1x, y1x, fmaf(g1y, y1y, g1z * y1z));
            sa1 = fmaf(WA.y * G0.y, y0, sa1);
            sb1 = fmaf(WB.y, d3, sb1);
            float cg = WC.y * G0.y;
            va1x = fmaf(cg, y1x, va1x); va1y = fmaf(cg, y1y, va1y); va1z = fmaf(cg, y1z, va1z);
            float dg = WD.y * y0;
            vb1x = fmaf(dg, g1x, vb1x); vb1y = fmaf(dg, g1y, vb1y); vb1z = fmaf(dg, g1z, vb1z);
        }
    }

    float a = attr[n];
    float scale = a * rsqrtf(deg[n]) * INV_SQRT128;
    float scb   = scale * INV_SQRT3;
    float4* sv = (float4*)(s_sv + w * 512);
    sv[2 * lane]      = make_float4(sa0 * scale, va0x * scale, va0y * scale, va0z * scale);
    sv[2 * lane + 1]  = make_float4(sa1 * scale, va1x * scale, va1y * scale, va1z * scale);
    sv[64 + 2 * lane]     = make_float4(sb0 * scb, vb0x * scale, vb0y * scale, vb0z * scale);
    sv[64 + 2 * lane + 1] = make_float4(sb1 * scb, vb1x * scale, vb1y * scale, vb1z * scale);
    __syncwarp();

    float o0a = 0.f, o0b = 0.f;
    float o1ax=0.f,o1ay=0.f,o1az=0.f, o1bx=0.f,o1by=0.f,o1bz=0.f;
#pragma unroll 4
    for (int u = 0; u < 128; u++) {
        float4 svu = sv[u];
        float2 w0 = *(const float2*)(sW0 + u * 64 + 2 * lane);
        float2 w1 = *(const float2*)(sW1 + u * 64 + 2 * lane);
        o0a = fmaf(svu.x, w0.x, o0a);
        o0b = fmaf(svu.x, w0.y, o0b);
        o1ax = fmaf(svu.y, w1.x, o1ax); o1ay = fmaf(svu.z, w1.x, o1ay); o1az = fmaf(svu.w, w1.x, o1az);
        o1bx = fmaf(svu.y, w1.y, o1bx); o1by = fmaf(svu.z, w1.y, o1by); o1bz = fmaf(svu.w, w1.y, o1bz);
    }

    float* op = out + n * 256;
    int k0 = 2 * lane;
    op[k0]     += C_X * o0a;
    op[k0 + 1] += C_X * o0b;
    int b0 = 64 + 3 * k0;
    op[b0 + 0] += C_X * o1ax; op[b0 + 1] += C_X * o1ay; op[b0 + 2] += C_X * o1az;
    op[b0 + 3] += C_X * o1bx; op[b0 + 4] += C_X * o1by; op[b0 + 5] += C_X * o1bz;
}

// ============================================================================
extern "C" void kernel_launch(void* const* d_in, const int* in_sizes, int n_in,
                              void* d_out, int out_size)
{
    const float* node_input = (const float*)d_in[0];
    const float* node_attr  = (const float*)d_in[1];
    const float* node_deg   = (const float*)d_in[2];
    const float* edge_attr  = (const float*)d_in[3];
    const float* elen       = (const float*)d_in[4];
    const float* W_li0      = (const float*)d_in[5];
    const float* W_li1      = (const float*)d_in[6];
    const float* W_lm0      = (const float*)d_in[7];
    const float* W_lm1      = (const float*)d_in[8];
    const float* W_mlp1     = (const float*)d_in[9];
    const float* W_mlp2     = (const float*)d_in[10];
    const float* W_lo0      = (const float*)d_in[11];
    const float* W_lo1      = (const float*)d_in[12];
    const int*   edge_src   = (const int*)d_in[13];
    const int*   edge_dst   = (const int*)d_in[14];
    float* out = (float*)d_out;

    static int attr_set = 0;
    if (!attr_set) {
        cudaFuncSetAttribute(k_node, cudaFuncAttributeMaxDynamicSharedMemorySize, 73760);
        cudaFuncSetAttribute(k_pull, cudaFuncAttributeMaxDynamicSharedMemorySize, 81920);
        cudaFuncSetAttribute(k_mlp_mma, cudaFuncAttributeMaxDynamicSharedMemorySize, MLP_SMEM);
        attr_set = 1;
    }

    k_zero<<<(N_NODES + 255) / 256, 256>>>();
    k_hist<<<N_EDGES / 256, 256>>>(edge_dst);
    k_scan<<<1, 1024>>>();
    k_fill<<<N_EDGES / 256, 256>>>(edge_dst, edge_src, edge_attr);
    k_prep<<<112, 256>>>(W_mlp2);
    k_mlp_mma<<<N_EDGES / 128, 256, MLP_SMEM>>>(elen, W_mlp1);
    k_node<<<N_NODES / 8, 256, 73760>>>(node_input, node_attr, node_deg,
                                        W_li0, W_li1, W_lm0, W_lm1, out);
    k_pull<<<N_NODES / 8, 256, 81920>>>(node_attr, node_deg,
                                        W_lo0, W_lo1, out);
}

// round 5
// speedup vs baseline: 1.0332x; 1.0332x over previous
#include <cuda_runtime.h>
#include <cuda_bf16.h>
#include <cuda_fp16.h>
#include <cstdint>

#define N_NODES 20000
#define N_EDGES 320000

// ---------------- device scratch ------------------------------------------
__device__ float  g_f [N_NODES * 256];      // f0|f1 (deg/attr/inv8 folded in)
__device__ __half g_ewh[N_EDGES * 256];     // per-edge MLP weights, DST-SORTED, fp16
__device__ int    g_cnt[N_NODES];
__device__ int    g_off[N_NODES + 1];
__device__ int    g_cur[N_NODES];
__device__ int    g_perm[N_EDGES];          // edge id -> sorted position
__device__ int    g_srcp[N_EDGES];          // sorted position -> src node
__device__ float4 g_eap[N_EDGES];           // sorted position -> edge_attr
__device__ __nv_bfloat16 g_W2t_h[256 * 112];
__device__ __nv_bfloat16 g_W2t_l[256 * 112];

// ---------------- constants -----------------------------------------------
#define INV8        0.125f
#define INV_SQRT10  0.3162277660168379f
#define INV10       0.1f
#define INV_SQRT3   0.5773502691896258f
#define INV_SQRT128 0.08838834764831845f
#define C_S         0.3826834323650898f
#define C_X         0.9238795325112867f

// ============================================================================
// K1: node self-interaction (unchanged)
// ============================================================================
__global__ __launch_bounds__(256) void k_node(
    const float* __restrict__ x, const float* __restrict__ attr,
    const float* __restrict__ deg,
    const float* __restrict__ Wli0, const float* __restrict__ Wli1,
    const float* __restrict__ Wlm0, const float* __restrict__ Wlm1,
    float* __restrict__ out)
{
    extern __shared__ float sm[];
    float* sWf0 = sm;
    float* sWf1 = sm + 4096;
    float* sWm0 = sm + 8192;
    float* sWm1 = sm + 12288;
    float* sx   = sm + 16384;     // 8 * 257

    int t = threadIdx.x;
    for (int i = t; i < 4096; i += 256) {
        sWf0[i] = Wli0[i]; sWf1[i] = Wli1[i];
        sWm0[i] = Wlm0[i]; sWm1[i] = Wlm1[i];
    }
    int nb = blockIdx.x * 8;
    for (int i = t; i < 8 * 256; i += 256) {
        int node = i >> 8, cc = i & 255;
        sx[node * 257 + cc] = x[(nb + node) * 256 + cc];
    }
    __syncthreads();

    int c = t;
    bool isS = (c < 64);
    int k = isS ? c : (c - 64) / 3;
    int m = isS ? 0 : (c - 64) % 3;
    int xoff = isS ? 0 : (64 + m);
    int xstr = isS ? 1 : 3;
    const float* wf = (isS ? sWf0 : sWf1) + k;
    const float* wm = (isS ? sWm0 : sWm1) + k;
    const float* xp = sx + xoff;

    float accf[8], accm[8];
#pragma unroll
    for (int i = 0; i < 8; i++) { accf[i] = 0.f; accm[i] = 0.f; }

#pragma unroll 4
    for (int u = 0; u < 64; u++) {
        float vf = wf[u * 64];
        float vm = wm[u * 64];
#pragma unroll
        for (int i = 0; i < 8; i++) {
            float xv = xp[i * 257 + u * xstr];
            accf[i] = fmaf(xv, vf, accf[i]);
            accm[i] = fmaf(xv, vm, accm[i]);
        }
    }
#pragma unroll
    for (int i = 0; i < 8; i++) {
        int n = nb + i;
        float a  = attr[n];
        float sf = INV8 * a * rsqrtf(deg[n]);
        float sc = INV8 * a * C_S;
        g_f[n * 256 + c] = accf[i] * sf;
        out[n * 256 + c] = accm[i] * sc;
    }
}

// ============================================================================
// CSR build kernels
// ============================================================================
__global__ __launch_bounds__(256) void k_zero() {
    int i = blockIdx.x * 256 + threadIdx.x;
    if (i < N_NODES) g_cnt[i] = 0;
}
__global__ __launch_bounds__(256) void k_hist(const int* __restrict__ dst) {
    int i = blockIdx.x * 256 + threadIdx.x;
    if (i < N_EDGES) atomicAdd(&g_cnt[dst[i]], 1);
}
__global__ __launch_bounds__(1024) void k_scan() {
    int t = threadIdx.x, lane = t & 31, wid = t >> 5;
    __shared__ int wsum[32];
    int base = t * 20;
    int loc[20];
    int s = 0;
#pragma unroll
    for (int j = 0; j < 20; j++) {
        int i = base + j;
        int v = (i < N_NODES) ? g_cnt[i] : 0;
        loc[j] = s; s += v;
    }
    int x = s;
#pragma unroll
    for (int d = 1; d < 32; d <<= 1) {
        int y = __shfl_up_sync(0xffffffffu, x, d);
        if (lane >= d) x += y;
    }
    if (lane == 31) wsum[wid] = x;
    __syncthreads();
    if (wid == 0) {
        int v2 = wsum[lane];
#pragma unroll
        for (int d = 1; d < 32; d <<= 1) {
            int y = __shfl_up_sync(0xffffffffu, v2, d);
            if (lane >= d) v2 += y;
        }
        wsum[lane] = v2;
    }
    __syncthreads();
    int excl = (wid ? wsum[wid - 1] : 0) + x - s;
#pragma unroll
    for (int j = 0; j < 20; j++) {
        int i = base + j;
        if (i < N_NODES) { g_off[i] = excl + loc[j]; g_cur[i] = excl + loc[j]; }
    }
    if (t == 1023) g_off[N_NODES] = excl + s;
}
__global__ __launch_bounds__(256) void k_fill(
    const int* __restrict__ dst, const int* __restrict__ src,
    const float* __restrict__ eattr)
{
    int i = blockIdx.x * 256 + threadIdx.x;
    if (i < N_EDGES) {
        int d = dst[i];
        int p = atomicAdd(&g_cur[d], 1);
        g_perm[i] = p;
        g_srcp[p] = src[i];
        g_eap[p]  = ((const float4*)eattr)[i];
    }
}

// ============================================================================
// K-prep: split W2^T into bf16 hi/lo, [n=256][k=112]
// ============================================================================
__global__ __launch_bounds__(256) void k_prep(const float* __restrict__ W2) {
    int idx = blockIdx.x * 256 + threadIdx.x;
    if (idx >= 256 * 112) return;
    int n = idx / 112, k = idx - n * 112;
    float v = (k < 100) ? W2[k * 256 + n] : 0.0f;
    __nv_bfloat16 h = __float2bfloat16(v);
    __nv_bfloat16 l = __float2bfloat16(v - __bfloat162float(h));
    g_W2t_h[idx] = h;
    g_W2t_l[idx] = l;
}

// ============================================================================
// K2 (HMMA): ew rows scattered to dst-sorted positions via g_perm (fp16 out)
// ============================================================================
#define RSTR 120
#define OFF_W1 0
#define OFF_AH 4096
#define OFF_AL 34816
#define OFF_BH 65536
#define OFF_BL 126976
#define MLP_SMEM 188416

__device__ __forceinline__ void mma16816(
    float& c0, float& c1, float& c2, float& c3,
    uint32_t a0, uint32_t a1, uint32_t a2, uint32_t a3,
    uint32_t b0, uint32_t b1)
{
    asm volatile(
        "mma.sync.aligned.m16n8k16.row.col.f32.bf16.bf16.f32 "
        "{%0,%1,%2,%3}, {%4,%5,%6,%7}, {%8,%9}, {%0,%1,%2,%3};"
        : "+f"(c0), "+f"(c1), "+f"(c2), "+f"(c3)
        : "r"(a0), "r"(a1), "r"(a2), "r"(a3), "r"(b0), "r"(b1));
}

__device__ __forceinline__ uint32_t pack_bf2(__nv_bfloat16 a, __nv_bfloat16 b) {
    return (uint32_t)__bfloat16_as_ushort(a) |
           ((uint32_t)__bfloat16_as_ushort(b) << 16);
}

__global__ __launch_bounds__(256, 1) void k_mlp_mma(
    const float* __restrict__ elen, const float* __restrict__ W1)
{
    extern __shared__ char smc[];
    float* sW1 = (float*)(smc + OFF_W1);
    __nv_bfloat16* sAh = (__nv_bfloat16*)(smc + OFF_AH);
    __nv_bfloat16* sAl = (__nv_bfloat16*)(smc + OFF_AL);
    __nv_bfloat16* sBh = (__nv_bfloat16*)(smc + OFF_BH);
    __nv_bfloat16* sBl = (__nv_bfloat16*)(smc + OFF_BL);

    int t = threadIdx.x, wid = t >> 5, lane = t & 31;
    int e0 = blockIdx.x * 128;

    for (int i = t; i < 1000; i += 256) sW1[i] = W1[i];
    {
        int n = t;
        const uint4* srcH = (const uint4*)(g_W2t_h + n * 112);
        const uint4* srcL = (const uint4*)(g_W2t_l + n * 112);
        uint4* dstH = (uint4*)(sBh + n * RSTR);
        uint4* dstL = (uint4*)(sBl + n * RSTR);
#pragma unroll
        for (int j = 0; j < 14; j++) { dstH[j] = srcH[j]; dstL[j] = srcL[j]; }
    }

    {
        int e  = t & 127;
        int kh = t >> 7;
        float el[10];
        const float* ep = elen + (e0 + e) * 10;
#pragma unroll
        for (int b = 0; b < 10; b++) el[b] = __ldg(ep + b);
        int kbase = 56 * kh;
#pragma unroll 1
        for (int kk = 0; kk < 56; kk += 2) {
            float h2[2];
#pragma unroll
            for (int jj = 0; jj < 2; jj++) {
                int k = kbase + kk + jj;
                float hv = 0.f;
                if (k < 100) {
                    float acc = 0.f;
#pragma unroll
                    for (int b = 0; b < 10; b++)
                        acc = fmaf(el[b], sW1[b * 100 + k], acc);
                    float xx = acc * INV_SQRT10;
                    hv = xx / (1.0f + __expf(-xx));
                }
                h2[jj] = hv;
            }
            __nv_bfloat16 h0 = __float2bfloat16(h2[0]);
            __nv_bfloat16 h1 = __float2bfloat16(h2[1]);
            __nv_bfloat16 l0 = __float2bfloat16(h2[0] - __bfloat162float(h0));
            __nv_bfloat16 l1 = __float2bfloat16(h2[1] - __bfloat162float(h1));
            int off = e * RSTR + kbase + kk;
            *(uint32_t*)(sAh + off) = pack_bf2(h0, h1);
            *(uint32_t*)(sAl + off) = pack_bf2(l0, l1);
        }
    }
    __syncthreads();

    int wm = wid & 3;
    int wn = wid >> 2;
    int rowA = 32 * wm + (lane >> 2);
    int kA   = (lane & 3) * 2;
    int rowB = 128 * wn + (lane >> 2);

    float acc[2][16][4];
#pragma unroll
    for (int mt = 0; mt < 2; mt++)
#pragma unroll
        for (int nt = 0; nt < 16; nt++)
#pragma unroll
            for (int j = 0; j < 4; j++) acc[mt][nt][j] = 0.f;

    const __nv_bfloat16* Aptr[3] = { sAh, sAh, sAl };
    const __nv_bfloat16* Bptr[3] = { sBh, sBl, sBh };

#pragma unroll 1
    for (int ks = 0; ks < 7; ks++) {
        int k0 = ks * 16 + kA;
#pragma unroll
        for (int p = 0; p < 3; p++) {
            const __nv_bfloat16* A = Aptr[p] + rowA * RSTR + k0;
            const __nv_bfloat16* B = Bptr[p] + rowB * RSTR + k0;
            uint32_t a[2][4];
#pragma unroll
            for (int mt = 0; mt < 2; mt++) {
                const __nv_bfloat16* Am = A + mt * 16 * RSTR;
                a[mt][0] = *(const uint32_t*)(Am);
                a[mt][1] = *(const uint32_t*)(Am + 8 * RSTR);
                a[mt][2] = *(const uint32_t*)(Am + 8);
                a[mt][3] = *(const uint32_t*)(Am + 8 * RSTR + 8);
            }
#pragma unroll
            for (int nt = 0; nt < 16; nt++) {
                const __nv_bfloat16* Bn = B + nt * 8 * RSTR;
                uint32_t b0 = *(const uint32_t*)(Bn);
                uint32_t b1 = *(const uint32_t*)(Bn + 8);
#pragma unroll
                for (int mt = 0; mt < 2; mt++)
                    mma16816(acc[mt][nt][0], acc[mt][nt][1],
                             acc[mt][nt][2], acc[mt][nt][3],
                             a[mt][0], a[mt][1], a[mt][2], a[mt][3], b0, b1);
            }
        }
    }

    // epilogue: fp16 pack, scatter rows to dst-sorted positions (streaming)
    int erow = e0 + 32 * wm + (lane >> 2);
    int col  = 128 * wn + (lane & 3) * 2;
    int prow[4];
#pragma unroll
    for (int j = 0; j < 4; j++) prow[j] = __ldg(&g_perm[erow + 8 * j]);
#pragma unroll
    for (int mt = 0; mt < 2; mt++) {
        __half* r0 = g_ewh + (size_t)prow[2 * mt]     * 256 + col;
        __half* r1 = g_ewh + (size_t)prow[2 * mt + 1] * 256 + col;
#pragma unroll
        for (int nt = 0; nt < 16; nt++) {
            int c = nt * 8;
            __half2 v0 = __floats2half2_rn(acc[mt][nt][0] * INV10,
                                           acc[mt][nt][1] * INV10);
            __half2 v1 = __floats2half2_rn(acc[mt][nt][2] * INV10,
                                           acc[mt][nt][3] * INV10);
            __stcs((__half2*)(r0 + c), v0);
            __stcs((__half2*)(r1 + c), v1);
        }
    }
}

// ============================================================================
// K3: pull kernel — fp16 ew stream, 2-deep prefetch, unroll 2
// ============================================================================
__global__ __launch_bounds__(256) void k_pull(
    const float* __restrict__ attr, const float* __restrict__ deg,
    const float* __restrict__ Wlo0, const float* __restrict__ Wlo1,
    float* __restrict__ out)
{
    extern __shared__ float sm[];
    float* sW0  = sm;
    float* sW1  = sm + 8192;
    float* s_sv = sm + 16384;

    int t = threadIdx.x;
    for (int i = t; i < 8192; i += 256) { sW0[i] = Wlo0[i]; sW1[i] = Wlo1[i]; }
    __syncthreads();

    int w = t >> 5, lane = t & 31;
    int n = blockIdx.x * 8 + w;
    int beg = g_off[n], end = g_off[n + 1];

    float sa0 = 0.f, sa1 = 0.f, sb0 = 0.f, sb1 = 0.f;
    float va0x=0.f,va0y=0.f,va0z=0.f, va1x=0.f,va1y=0.f,va1z=0.f;
    float vb0x=0.f,vb0y=0.f,vb0z=0.f, vb1x=0.f,vb1y=0.f,vb1z=0.f;

    int src0 = (beg     < end) ? __ldg(&g_srcp[beg])     : 0;
    int src1 = (beg + 1 < end) ? __ldg(&g_srcp[beg + 1]) : 0;

#pragma unroll 2
    for (int p = beg; p < end; p++) {
        int src = src0;
        src0 = src1;
        src1 = (p + 2 < end) ? __ldg(&g_srcp[p + 2]) : 0;
        float4 ea = __ldg(&g_eap[p]);
        float y0 = ea.x, y1x = ea.y, y1y = ea.z, y1z = ea.w;
        const float*  fp = g_f   + src * 256;
        const __half* wp = g_ewh + (size_t)p * 256;

        float2 G0 = *(const float2*)(fp + 2 * lane);
        float2 Ga = *(const float2*)(fp + 64 + 6 * lane);
        float2 Gb = *(const float2*)(fp + 64 + 6 * lane + 2);
        float2 Gc = *(const float2*)(fp + 64 + 6 * lane + 4);
        float2 WA = __half22float2(__ldcs((const __half2*)(wp + 2 * lane)));
        float2 WB = __half22float2(__ldcs((const __half2*)(wp + 64 + 2 * lane)));
        float2 WC = __half22float2(__ldcs((const __half2*)(wp + 128 + 2 * lane)));
        float2 WD = __half22float2(__ldcs((const __half2*)(wp + 192 + 2 * lane)));

        {
            float g1x = Ga.x, g1y = Ga.y, g1z = Gb.x;
            float d3 = fmaf(g1x, y1x, fmaf(g1y, y1y, g1z * y1z));
            sa0 = fmaf(WA.x * G0.x, y0, sa0);
            sb0 = fmaf(WB.x, d3, sb0);
            float cg = WC.x * G0.x;
            va0x = fmaf(cg, y1x, va0x); va0y = fmaf(cg, y1y, va0y); va0z = fmaf(cg, y1z, va0z);
            float dg = WD.x * y0;
            vb0x = fmaf(dg, g1x, vb0x); vb0y = fmaf(dg, g1y, vb0y); vb0z = fmaf(dg, g1z, vb0z);
        }
        {
            float g1x = Gb.y, g1y = Gc.x, g1z = Gc.y;
            float d3 = fmaf(g1x, y1x, fmaf(g1y, y1y, g1z * y1z));
            sa1 = fmaf(WA.y * G0.y, y0, sa1);
            sb1 = fmaf(WB.y, d3, sb1);
            float cg = WC.y * G0.y;
            va1x = fmaf(cg, y1x, va1x); va1y = fmaf(cg, y1y, va1y); va1z = fmaf(cg, y1z, va1z);
            float dg = WD.y * y0;
            vb1x = fmaf(dg, g1x, vb1x); vb1y = fmaf(dg, g1y, vb1y); vb1z = fmaf(dg, g1z, vb1z);
        }
    }

    float a = attr[n];
    float scale = a * rsqrtf(deg[n]) * INV_SQRT128;
    float scb   = scale * INV_SQRT3;
    float4* sv = (float4*)(s_sv + w * 512);
    sv[2 * lane]      = make_float4(sa0 * scale, va0x * scale, va0y * scale, va0z * scale);
    sv[2 * lane + 1]  = make_float4(sa1 * scale, va1x * scale, va1y * scale, va1z * scale);
    sv[64 + 2 * lane]     = make_float4(sb0 * scb, vb0x * scale, vb0y * scale, vb0z * scale);
    sv[64 + 2 * lane + 1] = make_float4(sb1 * scb, vb1x * scale, vb1y * scale, vb1z * scale);
    __syncwarp();

    float o0a = 0.f, o0b = 0.f;
    float o1ax=0.f,o1ay=0.f,o1az=0.f, o1bx=0.f,o1by=0.f,o1bz=0.f;
#pragma unroll 4
    for (int u = 0; u < 128; u++) {
        float4 svu = sv[u];
        float2 w0 = *(const float2*)(sW0 + u * 64 + 2 * lane);
        float2 w1 = *(const float2*)(sW1 + u * 64 + 2 * lane);
        o0a = fmaf(svu.x, w0.x, o0a);
        o0b = fmaf(svu.x, w0.y, o0b);
        o1ax = fmaf(svu.y, w1.x, o1ax); o1ay = fmaf(svu.z, w1.x, o1ay); o1az = fmaf(svu.w, w1.x, o1az);
        o1bx = fmaf(svu.y, w1.y, o1bx); o1by = fmaf(svu.z, w1.y, o1by); o1bz = fmaf(svu.w, w1.y, o1bz);
    }

    float* op = out + n * 256;
    int k0 = 2 * lane;
    op[k0]     += C_X * o0a;
    op[k0 + 1] += C_X * o0b;
    int b0 = 64 + 3 * k0;
    op[b0 + 0] += C_X * o1ax; op[b0 + 1] += C_X * o1ay; op[b0 + 2] += C_X * o1az;
    op[b0 + 3] += C_X * o1bx; op[b0 + 4] += C_X * o1by; op[b0 + 5] += C_X * o1bz;
}

// ============================================================================
extern "C" void kernel_launch(void* const* d_in, const int* in_sizes, int n_in,
                              void* d_out, int out_size)
{
    const float* node_input = (const float*)d_in[0];
    const float* node_attr  = (const float*)d_in[1];
    const float* node_deg   = (const float*)d_in[2];
    const float* edge_attr  = (const float*)d_in[3];
    const float* elen       = (const float*)d_in[4];
    const float* W_li0      = (const float*)d_in[5];
    const float* W_li1      = (const float*)d_in[6];
    const float* W_lm0      = (const float*)d_in[7];
    const float* W_lm1      = (const float*)d_in[8];
    const float* W_mlp1     = (const float*)d_in[9];
    const float* W_mlp2     = (const float*)d_in[10];
    const float* W_lo0      = (const float*)d_in[11];
    const float* W_lo1      = (const float*)d_in[12];
    const int*   edge_src   = (const int*)d_in[13];
    const int*   edge_dst   = (const int*)d_in[14];
    float* out = (float*)d_out;

    static int attr_set = 0;
    if (!attr_set) {
        cudaFuncSetAttribute(k_node, cudaFuncAttributeMaxDynamicSharedMemorySize, 73760);
        cudaFuncSetAttribute(k_pull, cudaFuncAttributeMaxDynamicSharedMemorySize, 81920);
        cudaFuncSetAttribute(k_mlp_mma, cudaFuncAttributeMaxDynamicSharedMemorySize, MLP_SMEM);
        attr_set = 1;
    }

    k_zero<<<(N_NODES + 255) / 256, 256>>>();
    k_hist<<<N_EDGES / 256, 256>>>(edge_dst);
    k_scan<<<1, 1024>>>();
    k_fill<<<N_EDGES / 256, 256>>>(edge_dst, edge_src, edge_attr);
    k_prep<<<112, 256>>>(W_mlp2);
    k_mlp_mma<<<N_EDGES / 128, 256, MLP_SMEM>>>(elen, W_mlp1);
    k_node<<<N_NODES / 8, 256, 73760>>>(node_input, node_attr, node_deg,
                                        W_li0, W_li1, W_lm0, W_lm1, out);
    k_pull<<<N_NODES / 8, 256, 81920>>>(node_attr, node_deg,
                                        W_lo0, W_lo1, out);
}

// round 6
// speedup vs baseline: 1.1699x; 1.1323x over previous
#include <cuda_runtime.h>
#include <cuda_fp16.h>
#include <cstdint>

#define N_NODES 20000
#define N_EDGES 320000

// ---------------- device scratch ------------------------------------------
__device__ float  g_f [N_NODES * 256];      // f0|f1 (deg/attr/inv8 folded in)
__device__ __half g_ewh[N_EDGES * 256];     // per-edge MLP weights, EDGE-ORDER, fp16
__device__ int    g_cnt[N_NODES];
__device__ int    g_off[N_NODES + 1];
__device__ int    g_cur[N_NODES];
__device__ int    g_eid[N_EDGES];           // sorted position -> edge id
__device__ int    g_srcp[N_EDGES];          // sorted position -> src node
__device__ float4 g_eap[N_EDGES];           // sorted position -> edge_attr
__device__ __half g_W2t_h[256 * 112];       // W2^T fp16 hi, [n][k]
__device__ __half g_W2t_l[256 * 112];       // W2^T fp16 lo

// ---------------- constants -----------------------------------------------
#define INV8        0.125f
#define INV_SQRT10  0.3162277660168379f
#define INV10       0.1f
#define INV_SQRT3   0.5773502691896258f
#define INV_SQRT128 0.08838834764831845f
#define C_S         0.3826834323650898f
#define C_X         0.9238795325112867f

// ============================================================================
// K1: node self-interaction (unchanged)
// ============================================================================
__global__ __launch_bounds__(256) void k_node(
    const float* __restrict__ x, const float* __restrict__ attr,
    const float* __restrict__ deg,
    const float* __restrict__ Wli0, const float* __restrict__ Wli1,
    const float* __restrict__ Wlm0, const float* __restrict__ Wlm1,
    float* __restrict__ out)
{
    extern __shared__ float sm[];
    float* sWf0 = sm;
    float* sWf1 = sm + 4096;
    float* sWm0 = sm + 8192;
    float* sWm1 = sm + 12288;
    float* sx   = sm + 16384;     // 8 * 257

    int t = threadIdx.x;
    for (int i = t; i < 4096; i += 256) {
        sWf0[i] = Wli0[i]; sWf1[i] = Wli1[i];
        sWm0[i] = Wlm0[i]; sWm1[i] = Wlm1[i];
    }
    int nb = blockIdx.x * 8;
    for (int i = t; i < 8 * 256; i += 256) {
        int node = i >> 8, cc = i & 255;
        sx[node * 257 + cc] = x[(nb + node) * 256 + cc];
    }
    __syncthreads();

    int c = t;
    bool isS = (c < 64);
    int k = isS ? c : (c - 64) / 3;
    int m = isS ? 0 : (c - 64) % 3;
    int xoff = isS ? 0 : (64 + m);
    int xstr = isS ? 1 : 3;
    const float* wf = (isS ? sWf0 : sWf1) + k;
    const float* wm = (isS ? sWm0 : sWm1) + k;
    const float* xp = sx + xoff;

    float accf[8], accm[8];
#pragma unroll
    for (int i = 0; i < 8; i++) { accf[i] = 0.f; accm[i] = 0.f; }

#pragma unroll 4
    for (int u = 0; u < 64; u++) {
        float vf = wf[u * 64];
        float vm = wm[u * 64];
#pragma unroll
        for (int i = 0; i < 8; i++) {
            float xv = xp[i * 257 + u * xstr];
            accf[i] = fmaf(xv, vf, accf[i]);
            accm[i] = fmaf(xv, vm, accm[i]);
        }
    }
#pragma unroll
    for (int i = 0; i < 8; i++) {
        int n = nb + i;
        float a  = attr[n];
        float sf = INV8 * a * rsqrtf(deg[n]);
        float sc = INV8 * a * C_S;
        g_f[n * 256 + c] = accf[i] * sf;
        out[n * 256 + c] = accm[i] * sc;
    }
}

// ============================================================================
// CSR build kernels
// ============================================================================
__global__ __launch_bounds__(256) void k_zero() {
    int i = blockIdx.x * 256 + threadIdx.x;
    if (i < N_NODES) g_cnt[i] = 0;
}
__global__ __launch_bounds__(256) void k_hist(const int* __restrict__ dst) {
    int i = blockIdx.x * 256 + threadIdx.x;
    if (i < N_EDGES) atomicAdd(&g_cnt[dst[i]], 1);
}
__global__ __launch_bounds__(1024) void k_scan() {
    int t = threadIdx.x, lane = t & 31, wid = t >> 5;
    __shared__ int wsum[32];
    int base = t * 20;
    int loc[20];
    int s = 0;
#pragma unroll
    for (int j = 0; j < 20; j++) {
        int i = base + j;
        int v = (i < N_NODES) ? g_cnt[i] : 0;
        loc[j] = s; s += v;
    }
    int x = s;
#pragma unroll
    for (int d = 1; d < 32; d <<= 1) {
        int y = __shfl_up_sync(0xffffffffu, x, d);
        if (lane >= d) x += y;
    }
    if (lane == 31) wsum[wid] = x;
    __syncthreads();
    if (wid == 0) {
        int v2 = wsum[lane];
#pragma unroll
        for (int d = 1; d < 32; d <<= 1) {
            int y = __shfl_up_sync(0xffffffffu, v2, d);
            if (lane >= d) v2 += y;
        }
        wsum[lane] = v2;
    }
    __syncthreads();
    int excl = (wid ? wsum[wid - 1] : 0) + x - s;
#pragma unroll
    for (int j = 0; j < 20; j++) {
        int i = base + j;
        if (i < N_NODES) { g_off[i] = excl + loc[j]; g_cur[i] = excl + loc[j]; }
    }
    if (t == 1023) g_off[N_NODES] = excl + s;
}
__global__ __launch_bounds__(256) void k_fill(
    const int* __restrict__ dst, const int* __restrict__ src,
    const float* __restrict__ eattr)
{
    int i = blockIdx.x * 256 + threadIdx.x;
    if (i < N_EDGES) {
        int d = dst[i];
        int p = atomicAdd(&g_cur[d], 1);
        g_eid[p]  = i;
        g_srcp[p] = src[i];
        g_eap[p]  = ((const float4*)eattr)[i];
    }
}

// ============================================================================
// K-prep: split W2^T into fp16 hi/lo, [n=256][k=112]
// ============================================================================
__global__ __launch_bounds__(256) void k_prep(const float* __restrict__ W2) {
    int idx = blockIdx.x * 256 + threadIdx.x;
    if (idx >= 256 * 112) return;
    int n = idx / 112, k = idx - n * 112;
    float v = (k < 100) ? W2[k * 256 + n] : 0.0f;
    __half h = __float2half_rn(v);
    __half l = __float2half_rn(v - __half2float(h));
    g_W2t_h[idx] = h;
    g_W2t_l[idx] = l;
}

// ============================================================================
// K2 (HMMA fp16, 2-pass, ldmatrix): ew = silu(elen@W1/sqrt10) @ W2 / 10
// D = A_fp16 * (Bh + Bl)   — A single fp16, B split fp16 hi/lo.
// Per block 128 edges x 256 outs, K=112 (7 k-steps x 2 passes = 14 MMA passes).
// ============================================================================
#define RSTR 120                       // padded row stride (fp16 elems, 240 B)
#define OFF_W1 0                       // 4000 B
#define OFF_A  4096                    // 128*240 = 30720
#define OFF_BH 34816                   // 256*240 = 61440
#define OFF_BL 96256                   // 61440
#define MLP_SMEM 157696

__device__ __forceinline__ uint32_t smem_u32(const void* p) {
    uint32_t a;
    asm("{ .reg .u64 t; cvta.to.shared.u64 t, %1; cvt.u32.u64 %0, t; }"
        : "=r"(a) : "l"(p));
    return a;
}
#define LDMX4(r, addr) \
    asm volatile("ldmatrix.sync.aligned.m8n8.x4.shared.b16 {%0,%1,%2,%3}, [%4];" \
        : "=r"((r)[0]), "=r"((r)[1]), "=r"((r)[2]), "=r"((r)[3]) \
        : "r"(addr))

__device__ __forceinline__ void mma16816h(
    float& c0, float& c1, float& c2, float& c3,
    uint32_t a0, uint32_t a1, uint32_t a2, uint32_t a3,
    uint32_t b0, uint32_t b1)
{
    asm volatile(
        "mma.sync.aligned.m16n8k16.row.col.f32.f16.f16.f32 "
        "{%0,%1,%2,%3}, {%4,%5,%6,%7}, {%8,%9}, {%0,%1,%2,%3};"
        : "+f"(c0), "+f"(c1), "+f"(c2), "+f"(c3)
        : "r"(a0), "r"(a1), "r"(a2), "r"(a3), "r"(b0), "r"(b1));
}

__global__ __launch_bounds__(256, 1) void k_mlp_mma(
    const float* __restrict__ elen, const float* __restrict__ W1)
{
    extern __shared__ char smc[];
    float*  sW1 = (float*)(smc + OFF_W1);
    __half* sA  = (__half*)(smc + OFF_A);

    int t = threadIdx.x, wid = t >> 5, lane = t & 31;
    int e0 = blockIdx.x * 128;

    for (int i = t; i < 1000; i += 256) sW1[i] = W1[i];
    {   // B copy: one row (112 fp16 = 14 uint4) per thread
        int n = t;
        const uint4* srcH = (const uint4*)(g_W2t_h + n * 112);
        const uint4* srcL = (const uint4*)(g_W2t_l + n * 112);
        uint4* dstH = (uint4*)(smc + OFF_BH + n * RSTR * 2);
        uint4* dstL = (uint4*)(smc + OFF_BL + n * RSTR * 2);
#pragma unroll
        for (int j = 0; j < 14; j++) { dstH[j] = srcH[j]; dstL[j] = srcL[j]; }
    }

    {   // layer 1 + silu -> A fp16
        int e  = t & 127;
        int kh = t >> 7;
        float el[10];
        const float* ep = elen + (e0 + e) * 10;
#pragma unroll
        for (int b = 0; b < 10; b++) el[b] = __ldg(ep + b);
        int kbase = 56 * kh;
#pragma unroll 1
        for (int kk = 0; kk < 56; kk += 2) {
            float h2[2];
#pragma unroll
            for (int jj = 0; jj < 2; jj++) {
                int k = kbase + kk + jj;
                float hv = 0.f;
                if (k < 100) {
                    float acc = 0.f;
#pragma unroll
                    for (int b = 0; b < 10; b++)
                        acc = fmaf(el[b], sW1[b * 100 + k], acc);
                    float xx = acc * INV_SQRT10;
                    hv = xx / (1.0f + __expf(-xx));
                }
                h2[jj] = hv;
            }
            *(uint32_t*)(sA + e * RSTR + kbase + kk) =
                __half2_raw(__floats2half2_rn(h2[0], h2[1])).x |
                ((uint32_t)__half2_raw(__floats2half2_rn(h2[0], h2[1])).y << 16);
        }
    }
    __syncthreads();

    int wm = wid & 3;                  // rows [32*wm, +32)
    int wn = wid >> 2;                 // cols [128*wn, +128)

    uint32_t sb = smem_u32(smc);
    // A ldmatrix lane address: row = (lane&15), k-half = (lane>>4)*8
    uint32_t aAddr = sb + OFF_A +
        (((32 * wm + (lane & 15)) * RSTR + (lane >> 4) * 8) << 1);
    // B ldmatrix lane address: n = (lane&7) + (lane>>4)*8, k-half = ((lane>>3)&1)*8
    uint32_t bOff = (((128 * wn + (lane & 7) + (lane >> 4) * 8) * RSTR
                      + ((lane >> 3) & 1) * 8) << 1);
    uint32_t bAddrH = sb + OFF_BH + bOff;
    uint32_t bAddrL = sb + OFF_BL + bOff;

    float acc[2][16][4];
#pragma unroll
    for (int mt = 0; mt < 2; mt++)
#pragma unroll
        for (int nt = 0; nt < 16; nt++)
#pragma unroll
            for (int j = 0; j < 4; j++) acc[mt][nt][j] = 0.f;

#pragma unroll 1
    for (int ks = 0; ks < 7; ks++) {
        uint32_t kb = ks * 32;         // bytes
        uint32_t a[2][4];
        LDMX4(a[0], aAddr + kb);
        LDMX4(a[1], aAddr + 16 * RSTR * 2 + kb);
#pragma unroll
        for (int pass = 0; pass < 2; pass++) {
            uint32_t base = (pass ? bAddrL : bAddrH) + kb;
#pragma unroll
            for (int j = 0; j < 8; j++) {
                uint32_t b[4];
                LDMX4(b, base + j * (16 * RSTR * 2));
#pragma unroll
                for (int mt = 0; mt < 2; mt++) {
                    mma16816h(acc[mt][2*j][0], acc[mt][2*j][1],
                              acc[mt][2*j][2], acc[mt][2*j][3],
                              a[mt][0], a[mt][1], a[mt][2], a[mt][3],
                              b[0], b[1]);
                    mma16816h(acc[mt][2*j+1][0], acc[mt][2*j+1][1],
                              acc[mt][2*j+1][2], acc[mt][2*j+1][3],
                              a[mt][0], a[mt][1], a[mt][2], a[mt][3],
                              b[2], b[3]);
                }
            }
        }
    }

    // epilogue: fp16 pack, edge-ordered streaming stores
    int erow = e0 + 32 * wm + (lane >> 2);
    int col  = 128 * wn + (lane & 3) * 2;
#pragma unroll
    for (int mt = 0; mt < 2; mt++) {
        __half* r0 = g_ewh + (size_t)(erow + mt * 16) * 256 + col;
        __half* r1 = r0 + 8 * 256;
#pragma unroll
        for (int nt = 0; nt < 16; nt++) {
            int c = nt * 8;
            __stcs((__half2*)(r0 + c),
                   __floats2half2_rn(acc[mt][nt][0] * INV10, acc[mt][nt][1] * INV10));
            __stcs((__half2*)(r1 + c),
                   __floats2half2_rn(acc[mt][nt][2] * INV10, acc[mt][nt][3] * INV10));
        }
    }
}

// ============================================================================
// K3: pull kernel — sorted src/eattr streams, eid-indirect fp16 ew
// ============================================================================
__global__ __launch_bounds__(256) void k_pull(
    const float* __restrict__ attr, const float* __restrict__ deg,
    const float* __restrict__ Wlo0, const float* __restrict__ Wlo1,
    float* __restrict__ out)
{
    extern __shared__ float sm[];
    float* sW0  = sm;
    float* sW1  = sm + 8192;
    float* s_sv = sm + 16384;

    int t = threadIdx.x;
    for (int i = t; i < 8192; i += 256) { sW0[i] = Wlo0[i]; sW1[i] = Wlo1[i]; }
    __syncthreads();

    int w = t >> 5, lane = t & 31;
    int n = blockIdx.x * 8 + w;
    int beg = g_off[n], end = g_off[n + 1];

    float sa0 = 0.f, sa1 = 0.f, sb0 = 0.f, sb1 = 0.f;
    float va0x=0.f,va0y=0.f,va0z=0.f, va1x=0.f,va1y=0.f,va1z=0.f;
    float vb0x=0.f,vb0y=0.f,vb0z=0.f, vb1x=0.f,vb1y=0.f,vb1z=0.f;

    int src0 = (beg     < end) ? __ldg(&g_srcp[beg])     : 0;
    int src1 = (beg + 1 < end) ? __ldg(&g_srcp[beg + 1]) : 0;
    int eid0 = (beg     < end) ? __ldg(&g_eid[beg])      : 0;
    int eid1 = (beg + 1 < end) ? __ldg(&g_eid[beg + 1])  : 0;

#pragma unroll 2
    for (int p = beg; p < end; p++) {
        int src = src0, e = eid0;
        src0 = src1; eid0 = eid1;
        src1 = (p + 2 < end) ? __ldg(&g_srcp[p + 2]) : 0;
        eid1 = (p + 2 < end) ? __ldg(&g_eid[p + 2])  : 0;
        float4 ea = __ldg(&g_eap[p]);
        float y0 = ea.x, y1x = ea.y, y1y = ea.z, y1z = ea.w;
        const float*  fp = g_f   + src * 256;
        const __half* wp = g_ewh + (size_t)e * 256;

        float2 G0 = *(const float2*)(fp + 2 * lane);
        float2 Ga = *(const float2*)(fp + 64 + 6 * lane);
        float2 Gb = *(const float2*)(fp + 64 + 6 * lane + 2);
        float2 Gc = *(const float2*)(fp + 64 + 6 * lane + 4);
        float2 WA = __half22float2(__ldcs((const __half2*)(wp + 2 * lane)));
        float2 WB = __half22float2(__ldcs((const __half2*)(wp + 64 + 2 * lane)));
        float2 WC = __half22float2(__ldcs((const __half2*)(wp + 128 + 2 * lane)));
        float2 WD = __half22float2(__ldcs((const __half2*)(wp + 192 + 2 * lane)));

        {
            float g1x = Ga.x, g1y = Ga.y, g1z = Gb.x;
            float d3 = fmaf(g1x, y1x, fmaf(g1y, y1y, g1z * y1z));
            sa0 = fmaf(WA.x * G0.x, y0, sa0);
            sb0 = fmaf(WB.x, d3, sb0);
            float cg = WC.x * G0.x;
            va0x = fmaf(cg, y1x, va0x); va0y = fmaf(cg, y1y, va0y); va0z = fmaf(cg, y1z, va0z);
            float dg = WD.x * y0;
            vb0x = fmaf(dg, g1x, vb0x); vb0y = fmaf(dg, g1y, vb0y); vb0z = fmaf(dg, g1z, vb0z);
        }
        {
            float g1x = Gb.y, g1y = Gc.x, g1z = Gc.y;
            float d3 = fmaf(g1x, y1x, fmaf(g1y, y1y, g1z * y1z));
            sa1 = fmaf(WA.y * G0.y, y0, sa1);
            sb1 = fmaf(WB.y, d3, sb1);
            float cg = WC.y * G0.y;
            va1x = fmaf(cg, y1x, va1x); va1y = fmaf(cg, y1y, va1y); va1z = fmaf(cg, y1z, va1z);
            float dg = WD.y * y0;
            vb1x = fmaf(dg, g1x, vb1x); vb1y = fmaf(dg, g1y, vb1y); vb1z = fmaf(dg, g1z, vb1z);
        }
    }

    float a = attr[n];
    float scale = a * rsqrtf(deg[n]) * INV_SQRT128;
    float scb   = scale * INV_SQRT3;
    float4* sv = (float4*)(s_sv + w * 512);
    sv[2 * lane]      = make_float4(sa0 * scale, va0x * scale, va0y * scale, va0z * scale);
    sv[2 * lane + 1]  = make_float4(sa1 * scale, va1x * scale, va1y * scale, va1z * scale);
    sv[64 + 2 * lane]     = make_float4(sb0 * scb, vb0x * scale, vb0y * scale, vb0z * scale);
    sv[64 + 2 * lane + 1] = make_float4(sb1 * scb, vb1x * scale, vb1y * scale, vb1z * scale);
    __syncwarp();

    float o0a = 0.f, o0b = 0.f;
    float o1ax=0.f,o1ay=0.f,o1az=0.f, o1bx=0.f,o1by=0.f,o1bz=0.f;
#pragma unroll 4
    for (int u = 0; u < 128; u++) {
        float4 svu = sv[u];
        float2 w0 = *(const float2*)(sW0 + u * 64 + 2 * lane);
        float2 w1 = *(const float2*)(sW1 + u * 64 + 2 * lane);
        o0a = fmaf(svu.x, w0.x, o0a);
        o0b = fmaf(svu.x, w0.y, o0b);
        o1ax = fmaf(svu.y, w1.x, o1ax); o1ay = fmaf(svu.z, w1.x, o1ay); o1az = fmaf(svu.w, w1.x, o1az);
        o1bx = fmaf(svu.y, w1.y, o1bx); o1by = fmaf(svu.z, w1.y, o1by); o1bz = fmaf(svu.w, w1.y, o1bz);
    }

    float* op = out + n * 256;
    int k0 = 2 * lane;
    op[k0]     += C_X * o0a;
    op[k0 + 1] += C_X * o0b;
    int b0 = 64 + 3 * k0;
    op[b0 + 0] += C_X * o1ax; op[b0 + 1] += C_X * o1ay; op[b0 + 2] += C_X * o1az;
    op[b0 + 3] += C_X * o1bx; op[b0 + 4] += C_X * o1by; op[b0 + 5] += C_X * o1bz;
}

// ============================================================================
extern "C" void kernel_launch(void* const* d_in, const int* in_sizes, int n_in,
                              void* d_out, int out_size)
{
    const float* node_input = (const float*)d_in[0];
    const float* node_attr  = (const float*)d_in[1];
    const float* node_deg   = (const float*)d_in[2];
    const float* edge_attr  = (const float*)d_in[3];
    const float* elen       = (const float*)d_in[4];
    const float* W_li0      = (const float*)d_in[5];
    const float* W_li1      = (const float*)d_in[6];
    const float* W_lm0      = (const float*)d_in[7];
    const float* W_lm1      = (const float*)d_in[8];
    const float* W_mlp1     = (const float*)d_in[9];
    const float* W_mlp2     = (const float*)d_in[10];
    const float* W_lo0      = (const float*)d_in[11];
    const float* W_lo1      = (const float*)d_in[12];
    const int*   edge_src   = (const int*)d_in[13];
    const int*   edge_dst   = (const int*)d_in[14];
    float* out = (float*)d_out;

    static int attr_set = 0;
    if (!attr_set) {
        cudaFuncSetAttribute(k_node, cudaFuncAttributeMaxDynamicSharedMemorySize, 73760);
        cudaFuncSetAttribute(k_pull, cudaFuncAttributeMaxDynamicSharedMemorySize, 81920);
        cudaFuncSetAttribute(k_mlp_mma, cudaFuncAttributeMaxDynamicSharedMemorySize, MLP_SMEM);
        attr_set = 1;
    }

    // order chosen so k_mlp_mma is launch #4 (the ncu-captured slot)
    k_zero<<<(N_NODES + 255) / 256, 256>>>();
    k_hist<<<N_EDGES / 256, 256>>>(edge_dst);
    k_prep<<<112, 256>>>(W_mlp2);
    k_mlp_mma<<<N_EDGES / 128, 256, MLP_SMEM>>>(elen, W_mlp1);
    k_scan<<<1, 1024>>>();
    k_fill<<<N_EDGES / 256, 256>>>(edge_dst, edge_src, edge_attr);
    k_node<<<N_NODES / 8, 256, 73760>>>(node_input, node_attr, node_deg,
                                        W_li0, W_li1, W_lm0, W_lm1, out);
    k_pull<<<N_NODES / 8, 256, 81920>>>(node_attr, node_deg,
                                        W_lo0, W_lo1, out);
}

// round 8
// speedup vs baseline: 1.1937x; 1.0203x over previous
#include <cuda_runtime.h>
#include <cuda_fp16.h>
#include <cstdint>

#define N_NODES 20000
#define N_EDGES 320000

// ---------------- device scratch ------------------------------------------
__device__ float  g_f [N_NODES * 256];      // f0|f1 (deg/attr/inv8 folded in)
__device__ __half g_ewh[N_EDGES * 256];     // per-edge MLP weights, EDGE-ORDER, fp16
__device__ int    g_cnt[N_NODES];
__device__ int    g_off[N_NODES + 1];
__device__ int    g_cur[N_NODES];
__device__ int    g_eid[N_EDGES];           // sorted position -> edge id
__device__ int    g_srcp[N_EDGES];          // sorted position -> src node
__device__ float4 g_eap[N_EDGES];           // sorted position -> edge_attr
__device__ __half g_W2t_h[256 * 112];       // W2^T fp16 hi, [n][k]
__device__ __half g_W2t_l[256 * 112];       // W2^T fp16 lo

// ---------------- constants -----------------------------------------------
#define INV8        0.125f
#define INV_SQRT10  0.3162277660168379f
#define INV10       0.1f
#define INV_SQRT3   0.5773502691896258f
#define INV_SQRT128 0.08838834764831845f
#define C_S         0.3826834323650898f
#define C_X         0.9238795325112867f

// ============================================================================
// K1: node self-interaction (unchanged)
// ============================================================================
__global__ __launch_bounds__(256) void k_node(
    const float* __restrict__ x, const float* __restrict__ attr,
    const float* __restrict__ deg,
    const float* __restrict__ Wli0, const float* __restrict__ Wli1,
    const float* __restrict__ Wlm0, const float* __restrict__ Wlm1,
    float* __restrict__ out)
{
    extern __shared__ float sm[];
    float* sWf0 = sm;
    float* sWf1 = sm + 4096;
    float* sWm0 = sm + 8192;
    float* sWm1 = sm + 12288;
    float* sx   = sm + 16384;     // 8 * 257

    int t = threadIdx.x;
    for (int i = t; i < 4096; i += 256) {
        sWf0[i] = Wli0[i]; sWf1[i] = Wli1[i];
        sWm0[i] = Wlm0[i]; sWm1[i] = Wlm1[i];
    }
    int nb = blockIdx.x * 8;
    for (int i = t; i < 8 * 256; i += 256) {
        int node = i >> 8, cc = i & 255;
        sx[node * 257 + cc] = x[(nb + node) * 256 + cc];
    }
    __syncthreads();

    int c = t;
    bool isS = (c < 64);
    int k = isS ? c : (c - 64) / 3;
    int m = isS ? 0 : (c - 64) % 3;
    int xoff = isS ? 0 : (64 + m);
    int xstr = isS ? 1 : 3;
    const float* wf = (isS ? sWf0 : sWf1) + k;
    const float* wm = (isS ? sWm0 : sWm1) + k;
    const float* xp = sx + xoff;

    float accf[8], accm[8];
#pragma unroll
    for (int i = 0; i < 8; i++) { accf[i] = 0.f; accm[i] = 0.f; }

#pragma unroll 4
    for (int u = 0; u < 64; u++) {
        float vf = wf[u * 64];
        float vm = wm[u * 64];
#pragma unroll
        for (int i = 0; i < 8; i++) {
            float xv = xp[i * 257 + u * xstr];
            accf[i] = fmaf(xv, vf, accf[i]);
            accm[i] = fmaf(xv, vm, accm[i]);
        }
    }
#pragma unroll
    for (int i = 0; i < 8; i++) {
        int n = nb + i;
        float a  = attr[n];
        float sf = INV8 * a * rsqrtf(deg[n]);
        float sc = INV8 * a * C_S;
        g_f[n * 256 + c] = accf[i] * sf;
        out[n * 256 + c] = accm[i] * sc;
    }
}

// ============================================================================
// CSR build kernels (unchanged)
// ============================================================================
__global__ __launch_bounds__(256) void k_zero() {
    int i = blockIdx.x * 256 + threadIdx.x;
    if (i < N_NODES) g_cnt[i] = 0;
}
__global__ __launch_bounds__(256) void k_hist(const int* __restrict__ dst) {
    int i = blockIdx.x * 256 + threadIdx.x;
    if (i < N_EDGES) atomicAdd(&g_cnt[dst[i]], 1);
}
__global__ __launch_bounds__(1024) void k_scan() {
    int t = threadIdx.x, lane = t & 31, wid = t >> 5;
    __shared__ int wsum[32];
    int base = t * 20;
    int loc[20];
    int s = 0;
#pragma unroll
    for (int j = 0; j < 20; j++) {
        int i = base + j;
        int v = (i < N_NODES) ? g_cnt[i] : 0;
        loc[j] = s; s += v;
    }
    int x = s;
#pragma unroll
    for (int d = 1; d < 32; d <<= 1) {
        int y = __shfl_up_sync(0xffffffffu, x, d);
        if (lane >= d) x += y;
    }
    if (lane == 31) wsum[wid] = x;
    __syncthreads();
    if (wid == 0) {
        int v2 = wsum[lane];
#pragma unroll
        for (int d = 1; d < 32; d <<= 1) {
            int y = __shfl_up_sync(0xffffffffu, v2, d);
            if (lane >= d) v2 += y;
        }
        wsum[lane] = v2;
    }
    __syncthreads();
    int excl = (wid ? wsum[wid - 1] : 0) + x - s;
#pragma unroll
    for (int j = 0; j < 20; j++) {
        int i = base + j;
        if (i < N_NODES) { g_off[i] = excl + loc[j]; g_cur[i] = excl + loc[j]; }
    }
    if (t == 1023) g_off[N_NODES] = excl + s;
}
__global__ __launch_bounds__(256) void k_fill(
    const int* __restrict__ dst, const int* __restrict__ src,
    const float* __restrict__ eattr)
{
    int i = blockIdx.x * 256 + threadIdx.x;
    if (i < N_EDGES) {
        int d = dst[i];
        int p = atomicAdd(&g_cur[d], 1);
        g_eid[p]  = i;
        g_srcp[p] = src[i];
        g_eap[p]  = ((const float4*)eattr)[i];
    }
}

// ============================================================================
// K-prep: W2^T to fp16 hi/lo, [n=256][k=112]
// ============================================================================
__global__ __launch_bounds__(256) void k_prep(const float* __restrict__ W2) {
    int idx = blockIdx.x * 256 + threadIdx.x;
    if (idx >= 256 * 112) return;
    int n = idx / 112, k = idx - n * 112;
    float v = (k < 100) ? W2[k * 256 + n] : 0.0f;
    __half h = __float2half_rn(v);
    __half l = __float2half_rn(v - __half2float(h));
    g_W2t_h[idx] = h;
    g_W2t_l[idx] = l;
}

// ============================================================================
// K2 (HMMA fp16, A single x B hi/lo 2-pass): ew = silu(elen@W1/sqrt10)@W2/10
// Block tile 128 edges x 128 cols (N split over 2 blocks). Warp tile 32x64.
// smem ~94KB, ~110 regs -> 2 CTAs/SM.
// ============================================================================
#define RSTR 120                       // padded row stride (fp16 elems, 240 B)
#define OFF_W1 0                       // 4000 B
#define OFF_A  4096                    // 128*240 = 30720
#define OFF_BH 34816                   // 30720
#define OFF_BL 65536                   // 30720
#define MLP_SMEM 96256

__device__ __forceinline__ uint32_t smem_u32(const void* p) {
    uint32_t a;
    asm("{ .reg .u64 t; cvta.to.shared.u64 t, %1; cvt.u32.u64 %0, t; }"
        : "=r"(a) : "l"(p));
    return a;
}
#define LDMX4(r, addr) \
    asm volatile("ldmatrix.sync.aligned.m8n8.x4.shared.b16 {%0,%1,%2,%3}, [%4];" \
        : "=r"((r)[0]), "=r"((r)[1]), "=r"((r)[2]), "=r"((r)[3]) \
        : "r"(addr))

__device__ __forceinline__ void mma16816h(
    float& c0, float& c1, float& c2, float& c3,
    uint32_t a0, uint32_t a1, uint32_t a2, uint32_t a3,
    uint32_t b0, uint32_t b1)
{
    asm volatile(
        "mma.sync.aligned.m16n8k16.row.col.f32.f16.f16.f32 "
        "{%0,%1,%2,%3}, {%4,%5,%6,%7}, {%8,%9}, {%0,%1,%2,%3};"
        : "+f"(c0), "+f"(c1), "+f"(c2), "+f"(c3)
        : "r"(a0), "r"(a1), "r"(a2), "r"(a3), "r"(b0), "r"(b1));
}

__global__ __launch_bounds__(256, 2) void k_mlp_mma(
    const float* __restrict__ elen, const float* __restrict__ W1)
{
    extern __shared__ char smc[];
    float*  sW1 = (float*)(smc + OFF_W1);
    __half* sA  = (__half*)(smc + OFF_A);

    int t = threadIdx.x, wid = t >> 5, lane = t & 31;
    int e0 = (blockIdx.x >> 1) * 128;
    int nb = (blockIdx.x & 1) * 128;   // which 128-col half of the 256 outputs

    for (int i = t; i < 1000; i += 256) sW1[i] = W1[i];
    {   // B copy: 128 rows each of Bh and Bl (cols nb..nb+127), 2 thr/row
        int n_local = t >> 1, half = t & 1;
        int goff = (nb + n_local) * 112 + half * 56;
        const uint4* srcH = (const uint4*)(g_W2t_h + goff);
        const uint4* srcL = (const uint4*)(g_W2t_l + goff);
        uint4* dstH = (uint4*)(smc + OFF_BH + n_local * RSTR * 2 + half * 112);
        uint4* dstL = (uint4*)(smc + OFF_BL + n_local * RSTR * 2 + half * 112);
#pragma unroll
        for (int j = 0; j < 7; j++) { dstH[j] = srcH[j]; dstL[j] = srcL[j]; }
    }

    {   // layer 1 + silu -> A fp16
        int e  = t & 127;
        int kh = t >> 7;
        float el[10];
        const float* ep = elen + (e0 + e) * 10;
#pragma unroll
        for (int b = 0; b < 10; b++) el[b] = __ldg(ep + b);
        int kbase = 56 * kh;
#pragma unroll 1
        for (int kk = 0; kk < 56; kk += 2) {
            float h2[2];
#pragma unroll
            for (int jj = 0; jj < 2; jj++) {
                int k = kbase + kk + jj;
                float hv = 0.f;
                if (k < 100) {
                    float acc = 0.f;
#pragma unroll
                    for (int b = 0; b < 10; b++)
                        acc = fmaf(el[b], sW1[b * 100 + k], acc);
                    float xx = acc * INV_SQRT10;
                    hv = xx / (1.0f + __expf(-xx));
                }
                h2[jj] = hv;
            }
            __half2 hh = __floats2half2_rn(h2[0], h2[1]);
            *(__half2*)(sA + e * RSTR + kbase + kk) = hh;
        }
    }
    __syncthreads();

    int wm = wid & 3;                  // rows [32*wm, +32)
    int wn = wid >> 2;                 // cols [64*wn, +64) within this half

    uint32_t sb = smem_u32(smc);
    uint32_t aAddr = sb + OFF_A +
        (((32 * wm + (lane & 15)) * RSTR + (lane >> 4) * 8) << 1);
    uint32_t bOff = (((64 * wn + (lane & 7) + (lane >> 4) * 8) * RSTR
                      + ((lane >> 3) & 1) * 8) << 1);
    uint32_t bAddrH = sb + OFF_BH + bOff;
    uint32_t bAddrL = sb + OFF_BL + bOff;

    float acc[2][8][4];
#pragma unroll
    for (int mt = 0; mt < 2; mt++)
#pragma unroll
        for (int nt = 0; nt < 8; nt++)
#pragma unroll
            for (int j = 0; j < 4; j++) acc[mt][nt][j] = 0.f;

#pragma unroll 1
    for (int ks = 0; ks < 7; ks++) {
        uint32_t kb = ks * 32;         // bytes
        uint32_t a[2][4];
        LDMX4(a[0], aAddr + kb);
        LDMX4(a[1], aAddr + 16 * RSTR * 2 + kb);
#pragma unroll
        for (int pass = 0; pass < 2; pass++) {
            uint32_t base = (pass ? bAddrL : bAddrH) + kb;
#pragma unroll
            for (int j = 0; j < 4; j++) {
                uint32_t b[4];
                LDMX4(b, base + j * (16 * RSTR * 2));
#pragma unroll
                for (int mt = 0; mt < 2; mt++) {
                    mma16816h(acc[mt][2*j][0], acc[mt][2*j][1],
                              acc[mt][2*j][2], acc[mt][2*j][3],
                              a[mt][0], a[mt][1], a[mt][2], a[mt][3],
                              b[0], b[1]);
                    mma16816h(acc[mt][2*j+1][0], acc[mt][2*j+1][1],
                              acc[mt][2*j+1][2], acc[mt][2*j+1][3],
                              a[mt][0], a[mt][1], a[mt][2], a[mt][3],
                              b[2], b[3]);
                }
            }
        }
    }

    // epilogue: fp16 pack, streaming stores
    int erow = e0 + 32 * wm + (lane >> 2);
    int col  = nb + 64 * wn + (lane & 3) * 2;
#pragma unroll
    for (int mt = 0; mt < 2; mt++) {
        __half* r0 = g_ewh + (size_t)(erow + mt * 16) * 256 + col;
        __half* r1 = r0 + 8 * 256;
#pragma unroll
        for (int nt = 0; nt < 8; nt++) {
            int c = nt * 8;
            __stcs((__half2*)(r0 + c),
                   __floats2half2_rn(acc[mt][nt][0] * INV10, acc[mt][nt][1] * INV10));
            __stcs((__half2*)(r1 + c),
                   __floats2half2_rn(acc[mt][nt][2] * INV10, acc[mt][nt][3] * INV10));
        }
    }
}

// ============================================================================
// K3: pull kernel (unchanged)
// ============================================================================
__global__ __launch_bounds__(256) void k_pull(
    const float* __restrict__ attr, const float* __restrict__ deg,
    const float* __restrict__ Wlo0, const float* __restrict__ Wlo1,
    float* __restrict__ out)
{
    extern __shared__ float sm[];
    float* sW0  = sm;
    float* sW1  = sm + 8192;
    float* s_sv = sm + 16384;

    int t = threadIdx.x;
    for (int i = t; i < 8192; i += 256) { sW0[i] = Wlo0[i]; sW1[i] = Wlo1[i]; }
    __syncthreads();

    int w = t >> 5, lane = t & 31;
    int n = blockIdx.x * 8 + w;
    int beg = g_off[n], end = g_off[n + 1];

    float sa0 = 0.f, sa1 = 0.f, sb0 = 0.f, sb1 = 0.f;
    float va0x=0.f,va0y=0.f,va0z=0.f, va1x=0.f,va1y=0.f,va1z=0.f;
    float vb0x=0.f,vb0y=0.f,vb0z=0.f, vb1x=0.f,vb1y=0.f,vb1z=0.f;

    int src0 = (beg     < end) ? __ldg(&g_srcp[beg])     : 0;
    int src1 = (beg + 1 < end) ? __ldg(&g_srcp[beg + 1]) : 0;
    int eid0 = (beg     < end) ? __ldg(&g_eid[beg])      : 0;
    int eid1 = (beg + 1 < end) ? __ldg(&g_eid[beg + 1])  : 0;

#pragma unroll 2
    for (int p = beg; p < end; p++) {
        int src = src0, e = eid0;
        src0 = src1; eid0 = eid1;
        src1 = (p + 2 < end) ? __ldg(&g_srcp[p + 2]) : 0;
        eid1 = (p + 2 < end) ? __ldg(&g_eid[p + 2])  : 0;
        float4 ea = __ldg(&g_eap[p]);
        float y0 = ea.x, y1x = ea.y, y1y = ea.z, y1z = ea.w;
        const float*  fp = g_f   + src * 256;
        const __half* wp = g_ewh + (size_t)e * 256;

        float2 G0 = *(const float2*)(fp + 2 * lane);
        float2 Ga = *(const float2*)(fp + 64 + 6 * lane);
        float2 Gb = *(const float2*)(fp + 64 + 6 * lane + 2);
        float2 Gc = *(const float2*)(fp + 64 + 6 * lane + 4);
        float2 WA = __half22float2(__ldcs((const __half2*)(wp + 2 * lane)));
        float2 WB = __half22float2(__ldcs((const __half2*)(wp + 64 + 2 * lane)));
        float2 WC = __half22float2(__ldcs((const __half2*)(wp + 128 + 2 * lane)));
        float2 WD = __half22float2(__ldcs((const __half2*)(wp + 192 + 2 * lane)));

        {
            float g1x = Ga.x, g1y = Ga.y, g1z = Gb.x;
            float d3 = fmaf(g1x, y1x, fmaf(g1y, y1y, g1z * y1z));
            sa0 = fmaf(WA.x * G0.x, y0, sa0);
            sb0 = fmaf(WB.x, d3, sb0);
            float cg = WC.x * G0.x;
            va0x = fmaf(cg, y1x, va0x); va0y = fmaf(cg, y1y, va0y); va0z = fmaf(cg, y1z, va0z);
            float dg = WD.x * y0;
            vb0x = fmaf(dg, g1x, vb0x); vb0y = fmaf(dg, g1y, vb0y); vb0z = fmaf(dg, g1z, vb0z);
        }
        {
            float g1x = Gb.y, g1y = Gc.x, g1z = Gc.y;
            float d3 = fmaf(g1x, y1x, fmaf(g1y, y1y, g1z * y1z));
            sa1 = fmaf(WA.y * G0.y, y0, sa1);
            sb1 = fmaf(WB.y, d3, sb1);
            float cg = WC.y * G0.y;
            va1x = fmaf(cg, y1x, va1x); va1y = fmaf(cg, y1y, va1y); va1z = fmaf(cg, y1z, va1z);
            float dg = WD.y * y0;
            vb1x = fmaf(dg, g1x, vb1x); vb1y = fmaf(dg, g1y, vb1y); vb1z = fmaf(dg, g1z, vb1z);
        }
    }

    float a = attr[n];
    float scale = a * rsqrtf(deg[n]) * INV_SQRT128;
    float scb   = scale * INV_SQRT3;
    float4* sv = (float4*)(s_sv + w * 512);
    sv[2 * lane]      = make_float4(sa0 * scale, va0x * scale, va0y * scale, va0z * scale);
    sv[2 * lane + 1]  = make_float4(sa1 * scale, va1x * scale, va1y * scale, va1z * scale);
    sv[64 + 2 * lane]     = make_float4(sb0 * scb, vb0x * scale, vb0y * scale, vb0z * scale);
    sv[64 + 2 * lane + 1] = make_float4(sb1 * scb, vb1x * scale, vb1y * scale, vb1z * scale);
    __syncwarp();

    float o0a = 0.f, o0b = 0.f;
    float o1ax=0.f,o1ay=0.f,o1az=0.f, o1bx=0.f,o1by=0.f,o1bz=0.f;
#pragma unroll 4
    for (int u = 0; u < 128; u++) {
        float4 svu = sv[u];
        float2 w0 = *(const float2*)(sW0 + u * 64 + 2 * lane);
        float2 w1 = *(const float2*)(sW1 + u * 64 + 2 * lane);
        o0a = fmaf(svu.x, w0.x, o0a);
        o0b = fmaf(svu.x, w0.y, o0b);
        o1ax = fmaf(svu.y, w1.x, o1ax); o1ay = fmaf(svu.z, w1.x, o1ay); o1az = fmaf(svu.w, w1.x, o1az);
        o1bx = fmaf(svu.y, w1.y, o1bx); o1by = fmaf(svu.z, w1.y, o1by); o1bz = fmaf(svu.w, w1.y, o1bz);
    }

    float* op = out + n * 256;
    int k0 = 2 * lane;
    op[k0]     += C_X * o0a;
    op[k0 + 1] += C_X * o0b;
    int b0 = 64 + 3 * k0;
    op[b0 + 0] += C_X * o1ax; op[b0 + 1] += C_X * o1ay; op[b0 + 2] += C_X * o1az;
    op[b0 + 3] += C_X * o1bx; op[b0 + 4] += C_X * o1by; op[b0 + 5] += C_X * o1bz;
}

// ============================================================================
extern "C" void kernel_launch(void* const* d_in, const int* in_sizes, int n_in,
                              void* d_out, int out_size)
{
    const float* node_input = (const float*)d_in[0];
    const float* node_attr  = (const float*)d_in[1];
    const float* node_deg   = (const float*)d_in[2];
    const float* edge_attr  = (const float*)d_in[3];
    const float* elen       = (const float*)d_in[4];
    const float* W_li0      = (const float*)d_in[5];
    const float* W_li1      = (const float*)d_in[6];
    const float* W_lm0      = (const float*)d_in[7];
    const float* W_lm1      = (const float*)d_in[8];
    const float* W_mlp1     = (const float*)d_in[9];
    const float* W_mlp2     = (const float*)d_in[10];
    const float* W_lo0      = (const float*)d_in[11];
    const float* W_lo1      = (const float*)d_in[12];
    const int*   edge_src   = (const int*)d_in[13];
    const int*   edge_dst   = (const int*)d_in[14];
    float* out = (float*)d_out;

    static int attr_set = 0;
    if (!attr_set) {
        cudaFuncSetAttribute(k_node, cudaFuncAttributeMaxDynamicSharedMemorySize, 73760);
        cudaFuncSetAttribute(k_pull, cudaFuncAttributeMaxDynamicSharedMemorySize, 81920);
        cudaFuncSetAttribute(k_mlp_mma, cudaFuncAttributeMaxDynamicSharedMemorySize, MLP_SMEM);
        attr_set = 1;
    }

    // order keeps k_mlp_mma in the ncu-captured slot
    k_zero<<<(N_NODES + 255) / 256, 256>>>();
    k_hist<<<N_EDGES / 256, 256>>>(edge_dst);
    k_prep<<<112, 256>>>(W_mlp2);
    k_mlp_mma<<<(N_EDGES / 128) * 2, 256, MLP_SMEM>>>(elen, W_mlp1);
    k_scan<<<1, 1024>>>();
    k_fill<<<N_EDGES / 256, 256>>>(edge_dst, edge_src, edge_attr);
    k_node<<<N_NODES / 8, 256, 73760>>>(node_input, node_attr, node_deg,
                                        W_li0, W_li1, W_lm0, W_lm1, out);
    k_pull<<<N_NODES / 8, 256, 81920>>>(node_attr, node_deg,
                                        W_lo0, W_lo1, out);
}

// round 10
// speedup vs baseline: 1.3230x; 1.1083x over previous
#include <cuda_runtime.h>
#include <cuda_fp16.h>
#include <cstdint>

#define N_NODES 20000
#define N_EDGES 320000

// ---------------- device scratch ------------------------------------------
__device__ float  g_f [N_NODES * 256];      // f0|f1 (deg/attr/inv8 folded in)
__device__ __half g_ewh[N_EDGES * 256];     // per-edge MLP weights, EDGE-ORDER, fp16
__device__ int    g_cnt[N_NODES];
__device__ int    g_off[N_NODES + 1];
__device__ int    g_cur[N_NODES];
__device__ int    g_eid[N_EDGES];           // sorted position -> edge id
__device__ int    g_srcp[N_EDGES];          // sorted position -> src node
__device__ float4 g_eap[N_EDGES];           // sorted position -> edge_attr
__device__ __half g_W2t_h[256 * 112];       // W2^T fp16 hi, [n][k]
__device__ __half g_W2t_l[256 * 112];       // W2^T fp16 lo
__device__ __half g_W1t_h[112 * 16];        // W1^T fp16 hi, [n=hid pad112][k=basis pad16]
__device__ __half g_W1t_l[112 * 16];        // W1^T fp16 lo

// ---------------- constants -----------------------------------------------
#define INV8        0.125f
#define INV_SQRT10  0.3162277660168379f
#define INV10       0.1f
#define INV_SQRT3   0.5773502691896258f
#define INV_SQRT128 0.08838834764831845f
#define C_S         0.3826834323650898f
#define C_X         0.9238795325112867f

// ============================================================================
// K1: node self-interaction (unchanged)
// ============================================================================
__global__ __launch_bounds__(256) void k_node(
    const float* __restrict__ x, const float* __restrict__ attr,
    const float* __restrict__ deg,
    const float* __restrict__ Wli0, const float* __restrict__ Wli1,
    const float* __restrict__ Wlm0, const float* __restrict__ Wlm1,
    float* __restrict__ out)
{
    extern __shared__ float sm[];
    float* sWf0 = sm;
    float* sWf1 = sm + 4096;
    float* sWm0 = sm + 8192;
    float* sWm1 = sm + 12288;
    float* sx   = sm + 16384;     // 8 * 257

    int t = threadIdx.x;
    for (int i = t; i < 4096; i += 256) {
        sWf0[i] = Wli0[i]; sWf1[i] = Wli1[i];
        sWm0[i] = Wlm0[i]; sWm1[i] = Wlm1[i];
    }
    int nb = blockIdx.x * 8;
    for (int i = t; i < 8 * 256; i += 256) {
        int node = i >> 8, cc = i & 255;
        sx[node * 257 + cc] = x[(nb + node) * 256 + cc];
    }
    __syncthreads();

    int c = t;
    bool isS = (c < 64);
    int k = isS ? c : (c - 64) / 3;
    int m = isS ? 0 : (c - 64) % 3;
    int xoff = isS ? 0 : (64 + m);
    int xstr = isS ? 1 : 3;
    const float* wf = (isS ? sWf0 : sWf1) + k;
    const float* wm = (isS ? sWm0 : sWm1) + k;
    const float* xp = sx + xoff;

    float accf[8], accm[8];
#pragma unroll
    for (int i = 0; i < 8; i++) { accf[i] = 0.f; accm[i] = 0.f; }

#pragma unroll 4
    for (int u = 0; u < 64; u++) {
        float vf = wf[u * 64];
        float vm = wm[u * 64];
#pragma unroll
        for (int i = 0; i < 8; i++) {
            float xv = xp[i * 257 + u * xstr];
            accf[i] = fmaf(xv, vf, accf[i]);
            accm[i] = fmaf(xv, vm, accm[i]);
        }
    }
#pragma unroll
    for (int i = 0; i < 8; i++) {
        int n = nb + i;
        float a  = attr[n];
        float sf = INV8 * a * rsqrtf(deg[n]);
        float sc = INV8 * a * C_S;
        g_f[n * 256 + c] = accf[i] * sf;
        out[n * 256 + c] = accm[i] * sc;
    }
}

// ============================================================================
// CSR build kernels (unchanged)
// ============================================================================
__global__ __launch_bounds__(256) void k_zero() {
    int i = blockIdx.x * 256 + threadIdx.x;
    if (i < N_NODES) g_cnt[i] = 0;
}
__global__ __launch_bounds__(256) void k_hist(const int* __restrict__ dst) {
    int i = blockIdx.x * 256 + threadIdx.x;
    if (i < N_EDGES) atomicAdd(&g_cnt[dst[i]], 1);
}
__global__ __launch_bounds__(1024) void k_scan() {
    int t = threadIdx.x, lane = t & 31, wid = t >> 5;
    __shared__ int wsum[32];
    int base = t * 20;
    int loc[20];
    int s = 0;
#pragma unroll
    for (int j = 0; j < 20; j++) {
        int i = base + j;
        int v = (i < N_NODES) ? g_cnt[i] : 0;
        loc[j] = s; s += v;
    }
    int x = s;
#pragma unroll
    for (int d = 1; d < 32; d <<= 1) {
        int y = __shfl_up_sync(0xffffffffu, x, d);
        if (lane >= d) x += y;
    }
    if (lane == 31) wsum[wid] = x;
    __syncthreads();
    if (wid == 0) {
        int v2 = wsum[lane];
#pragma unroll
        for (int d = 1; d < 32; d <<= 1) {
            int y = __shfl_up_sync(0xffffffffu, v2, d);
            if (lane >= d) v2 += y;
        }
        wsum[lane] = v2;
    }
    __syncthreads();
    int excl = (wid ? wsum[wid - 1] : 0) + x - s;
#pragma unroll
    for (int j = 0; j < 20; j++) {
        int i = base + j;
        if (i < N_NODES) { g_off[i] = excl + loc[j]; g_cur[i] = excl + loc[j]; }
    }
    if (t == 1023) g_off[N_NODES] = excl + s;
}
__global__ __launch_bounds__(256) void k_fill(
    const int* __restrict__ dst, const int* __restrict__ src,
    const float* __restrict__ eattr)
{
    int i = blockIdx.x * 256 + threadIdx.x;
    if (i < N_EDGES) {
        int d = dst[i];
        int p = atomicAdd(&g_cur[d], 1);
        g_eid[p]  = i;
        g_srcp[p] = src[i];
        g_eap[p]  = ((const float4*)eattr)[i];
    }
}

// ============================================================================
// K-prep: W2^T fp16 hi/lo [256][112]  +  W1^T fp16 hi/lo [112][16]
// ============================================================================
__global__ __launch_bounds__(256) void k_prep(
    const float* __restrict__ W2, const float* __restrict__ W1)
{
    int idx = blockIdx.x * 256 + threadIdx.x;
    if (idx < 256 * 112) {
        int n = idx / 112, k = idx - n * 112;
        float v = (k < 100) ? W2[k * 256 + n] : 0.0f;
        __half h = __float2half_rn(v);
        g_W2t_h[idx] = h;
        g_W2t_l[idx] = __float2half_rn(v - __half2float(h));
    }
    int j = idx - 256 * 112;
    if (j >= 0 && j < 112 * 16) {
        int n = j >> 4, k = j & 15;
        float v = (k < 10 && n < 100) ? W1[k * 100 + n] : 0.0f;
        __half h = __float2half_rn(v);
        g_W1t_h[j] = h;
        g_W1t_l[j] = __float2half_rn(v - __half2float(h));
    }
}

// ============================================================================
// K2: layer-1 via HMMA (elen hi/lo x W1t hi/lo, 3 passes -> fp32-grade h),
// silu in regs -> A fp16; mainloop EXACT R8 shape (A single x B hi/lo,
// warp tile 32x64, 2-pass). smem 90KB -> 2 CTAs/SM.
// ============================================================================
#define RSTR 120                       // A/B row stride (fp16 elems, 240 B)
#define ESTR 24                        // layer-1 tile row stride (48 B)
#define OFF_A   0                      // 128*240 = 30720 (overlaid below)
#define OFF_ELH 0                      //   128*48 = 6144
#define OFF_ELL 6144                   //   6144
#define OFF_W1H 12288                  //   112*48 = 5376
#define OFF_W1L 17664                  //   5376  (total 23040 < 30720)
#define OFF_BH  30720                  // 30720
#define OFF_BL  61440                  // 30720
#define MLP_SMEM 92160

__device__ __forceinline__ uint32_t smem_u32(const void* p) {
    uint32_t a;
    asm("{ .reg .u64 t; cvta.to.shared.u64 t, %1; cvt.u32.u64 %0, t; }"
        : "=r"(a) : "l"(p));
    return a;
}
#define LDMX4(r, addr) \
    asm volatile("ldmatrix.sync.aligned.m8n8.x4.shared.b16 {%0,%1,%2,%3}, [%4];" \
        : "=r"((r)[0]), "=r"((r)[1]), "=r"((r)[2]), "=r"((r)[3]) \
        : "r"(addr))

__device__ __forceinline__ void mma16816h(
    float& c0, float& c1, float& c2, float& c3,
    uint32_t a0, uint32_t a1, uint32_t a2, uint32_t a3,
    uint32_t b0, uint32_t b1)
{
    asm volatile(
        "mma.sync.aligned.m16n8k16.row.col.f32.f16.f16.f32 "
        "{%0,%1,%2,%3}, {%4,%5,%6,%7}, {%8,%9}, {%0,%1,%2,%3};"
        : "+f"(c0), "+f"(c1), "+f"(c2), "+f"(c3)
        : "r"(a0), "r"(a1), "r"(a2), "r"(a3), "r"(b0), "r"(b1));
}

__device__ __forceinline__ float silu_f(float x) {
    return x / (1.0f + __expf(-x));
}

__global__ __launch_bounds__(256, 2) void k_mlp_mma(
    const float* __restrict__ elen)
{
    extern __shared__ char smc[];
    __half* sA = (__half*)(smc + OFF_A);

    int t = threadIdx.x, wid = t >> 5, lane = t & 31;
    int e0 = (blockIdx.x >> 1) * 128;
    int nb = (blockIdx.x & 1) * 128;   // which 128-col half of the 256 outputs

    // ---- stage layer-1 operand tiles ----
    if (t < 128) {                     // elen row t: 10 floats -> hi/lo fp16, pad 16
        const float* ep = elen + (size_t)(e0 + t) * 10;
        __half* dh = (__half*)(smc + OFF_ELH) + t * ESTR;
        __half* dl = (__half*)(smc + OFF_ELL) + t * ESTR;
#pragma unroll
        for (int b = 0; b < 10; b++) {
            float v = __ldg(ep + b);
            __half h = __float2half_rn(v);
            dh[b] = h;
            dl[b] = __float2half_rn(v - __half2float(h));
        }
#pragma unroll
        for (int b = 10; b < 16; b++) { dh[b] = __half(0.f); dl[b] = __half(0.f); }
    } else {                           // W1t copy: 112 rows x 16 halves hi+lo
        int r = t - 128;               // 128 threads for 112 rows x (hi,lo)
        if (r < 112) {
            const uint4* srcH = (const uint4*)(g_W1t_h + r * 16);
            const uint4* srcL = (const uint4*)(g_W1t_l + r * 16);
            uint4* dstH = (uint4*)((__half*)(smc + OFF_W1H) + r * ESTR);
            uint4* dstL = (uint4*)((__half*)(smc + OFF_W1L) + r * ESTR);
            dstH[0] = srcH[0]; dstH[1] = srcH[1];
            dstL[0] = srcL[0]; dstL[1] = srcL[1];
        }
    }
    {   // B copy: 128 rows each of Bh and Bl (cols nb..nb+127), 2 thr/row
        int n_local = t >> 1, half = t & 1;
        int goff = (nb + n_local) * 112 + half * 56;
        const uint4* srcH = (const uint4*)(g_W2t_h + goff);
        const uint4* srcL = (const uint4*)(g_W2t_l + goff);
        uint4* dstH = (uint4*)(smc + OFF_BH + n_local * RSTR * 2 + half * 112);
        uint4* dstL = (uint4*)(smc + OFF_BL + n_local * RSTR * 2 + half * 112);
#pragma unroll
        for (int j = 0; j < 7; j++) { dstH[j] = srcH[j]; dstL[j] = srcL[j]; }
    }
    __syncthreads();

    uint32_t sb = smem_u32(smc);

    // ---- layer-1 HMMA: warp wid owns edge rows [16*wid, +16) ----
    float hacc[14][4];
#pragma unroll
    for (int nt = 0; nt < 14; nt++)
#pragma unroll
        for (int j = 0; j < 4; j++) hacc[nt][j] = 0.f;
    {
        uint32_t aoff = (((16 * wid + (lane & 15)) * ESTR + (lane >> 4) * 8) << 1);
        uint32_t boff = ((((lane & 7) + (lane >> 4) * 8) * ESTR
                          + ((lane >> 3) & 1) * 8) << 1);
        uint32_t ah[4], al[4];
        LDMX4(ah, sb + OFF_ELH + aoff);
        LDMX4(al, sb + OFF_ELL + aoff);
#pragma unroll
        for (int p2 = 0; p2 < 7; p2++) {
            uint32_t bstep = p2 * (16 * ESTR * 2);
            uint32_t bh[4], bl[4];
            LDMX4(bh, sb + OFF_W1H + boff + bstep);
            LDMX4(bl, sb + OFF_W1L + boff + bstep);
            int n0 = 2 * p2, n1 = 2 * p2 + 1;
            mma16816h(hacc[n0][0], hacc[n0][1], hacc[n0][2], hacc[n0][3],
                      ah[0], ah[1], ah[2], ah[3], bh[0], bh[1]);
            mma16816h(hacc[n1][0], hacc[n1][1], hacc[n1][2], hacc[n1][3],
                      ah[0], ah[1], ah[2], ah[3], bh[2], bh[3]);
            mma16816h(hacc[n0][0], hacc[n0][1], hacc[n0][2], hacc[n0][3],
                      ah[0], ah[1], ah[2], ah[3], bl[0], bl[1]);
            mma16816h(hacc[n1][0], hacc[n1][1], hacc[n1][2], hacc[n1][3],
                      ah[0], ah[1], ah[2], ah[3], bl[2], bl[3]);
            mma16816h(hacc[n0][0], hacc[n0][1], hacc[n0][2], hacc[n0][3],
                      al[0], al[1], al[2], al[3], bh[0], bh[1]);
            mma16816h(hacc[n1][0], hacc[n1][1], hacc[n1][2], hacc[n1][3],
                      al[0], al[1], al[2], al[3], bh[2], bh[3]);
        }
    }
    __syncthreads();   // all reads of sEl/sW1t done; safe to overwrite with sA

    // ---- silu + store A tile ----
    {
        int row = 16 * wid + (lane >> 2);
#pragma unroll
        for (int nt = 0; nt < 14; nt++) {
            int col = nt * 8 + (lane & 3) * 2;
            float x0 = hacc[nt][0] * INV_SQRT10;
            float x1 = hacc[nt][1] * INV_SQRT10;
            float x2 = hacc[nt][2] * INV_SQRT10;
            float x3 = hacc[nt][3] * INV_SQRT10;
            *(__half2*)(sA + row * RSTR + col) =
                __floats2half2_rn(silu_f(x0), silu_f(x1));
            *(__half2*)(sA + (row + 8) * RSTR + col) =
                __floats2half2_rn(silu_f(x2), silu_f(x3));
        }
    }
    __syncthreads();

    // ---- mainloop: EXACT R8 shape (warp 32x64, A single, B hi/lo 2-pass) ----
    int wm = wid & 3;                  // rows [32*wm, +32)
    int wn = wid >> 2;                 // cols [64*wn, +64) within this half

    uint32_t aAddr = sb + OFF_A +
        (((32 * wm + (lane & 15)) * RSTR + (lane >> 4) * 8) << 1);
    uint32_t bOff = (((64 * wn + (lane & 7) + (lane >> 4) * 8) * RSTR
                      + ((lane >> 3) & 1) * 8) << 1);
    uint32_t bAddrH = sb + OFF_BH + bOff;
    uint32_t bAddrL = sb + OFF_BL + bOff;

    float acc[2][8][4];
#pragma unroll
    for (int mt = 0; mt < 2; mt++)
#pragma unroll
        for (int nt = 0; nt < 8; nt++)
#pragma unroll
            for (int j = 0; j < 4; j++) acc[mt][nt][j] = 0.f;

#pragma unroll 1
    for (int ks = 0; ks < 7; ks++) {
        uint32_t kb = ks * 32;         // bytes
        uint32_t a[2][4];
        LDMX4(a[0], aAddr + kb);
        LDMX4(a[1], aAddr + 16 * RSTR * 2 + kb);
#pragma unroll
        for (int pass = 0; pass < 2; pass++) {
            uint32_t base = (pass ? bAddrL : bAddrH) + kb;
#pragma unroll
            for (int j = 0; j < 4; j++) {
                uint32_t b[4];
                LDMX4(b, base + j * (16 * RSTR * 2));
#pragma unroll
                for (int mt = 0; mt < 2; mt++) {
                    mma16816h(acc[mt][2*j][0], acc[mt][2*j][1],
                              acc[mt][2*j][2], acc[mt][2*j][3],
                              a[mt][0], a[mt][1], a[mt][2], a[mt][3],
                              b[0], b[1]);
                    mma16816h(acc[mt][2*j+1][0], acc[mt][2*j+1][1],
                              acc[mt][2*j+1][2], acc[mt][2*j+1][3],
                              a[mt][0], a[mt][1], a[mt][2], a[mt][3],
                              b[2], b[3]);
                }
            }
        }
    }

    // epilogue: fp16 pack, streaming stores
    int erow = e0 + 32 * wm + (lane >> 2);
    int col  = nb + 64 * wn + (lane & 3) * 2;
#pragma unroll
    for (int mt = 0; mt < 2; mt++) {
        __half* r0 = g_ewh + (size_t)(erow + mt * 16) * 256 + col;
        __half* r1 = r0 + 8 * 256;
#pragma unroll
        for (int nt = 0; nt < 8; nt++) {
            int c = nt * 8;
            __stcs((__half2*)(r0 + c),
                   __floats2half2_rn(acc[mt][nt][0] * INV10, acc[mt][nt][1] * INV10));
            __stcs((__half2*)(r1 + c),
                   __floats2half2_rn(acc[mt][nt][2] * INV10, acc[mt][nt][3] * INV10));
        }
    }
}

// ============================================================================
// K3: pull kernel (unchanged from R8)
// ============================================================================
__global__ __launch_bounds__(256) void k_pull(
    const float* __restrict__ attr, const float* __restrict__ deg,
    const float* __restrict__ Wlo0, const float* __restrict__ Wlo1,
    float* __restrict__ out)
{
    extern __shared__ float sm[];
    float* sW0  = sm;
    float* sW1  = sm + 8192;
    float* s_sv = sm + 16384;

    int t = threadIdx.x;
    for (int i = t; i < 8192; i += 256) { sW0[i] = Wlo0[i]; sW1[i] = Wlo1[i]; }
    __syncthreads();

    int w = t >> 5, lane = t & 31;
    int n = blockIdx.x * 8 + w;
    int beg = g_off[n], end = g_off[n + 1];

    float sa0 = 0.f, sa1 = 0.f, sb0 = 0.f, sb1 = 0.f;
    float va0x=0.f,va0y=0.f,va0z=0.f, va1x=0.f,va1y=0.f,va1z=0.f;
    float vb0x=0.f,vb0y=0.f,vb0z=0.f, vb1x=0.f,vb1y=0.f,vb1z=0.f;

    int src0 = (beg     < end) ? __ldg(&g_srcp[beg])     : 0;
    int src1 = (beg + 1 < end) ? __ldg(&g_srcp[beg + 1]) : 0;
    int eid0 = (beg     < end) ? __ldg(&g_eid[beg])      : 0;
    int eid1 = (beg + 1 < end) ? __ldg(&g_eid[beg + 1])  : 0;

#pragma unroll 2
    for (int p = beg; p < end; p++) {
        int src = src0, e = eid0;
        src0 = src1; eid0 = eid1;
        src1 = (p + 2 < end) ? __ldg(&g_srcp[p + 2]) : 0;
        eid1 = (p + 2 < end) ? __ldg(&g_eid[p + 2])  : 0;
        float4 ea = __ldg(&g_eap[p]);
        float y0 = ea.x, y1x = ea.y, y1y = ea.z, y1z = ea.w;
        const float*  fp = g_f   + src * 256;
        const __half* wp = g_ewh + (size_t)e * 256;

        float2 G0 = *(const float2*)(fp + 2 * lane);
        float2 Ga = *(const float2*)(fp + 64 + 6 * lane);
        float2 Gb = *(const float2*)(fp + 64 + 6 * lane + 2);
        float2 Gc = *(const float2*)(fp + 64 + 6 * lane + 4);
        float2 WA = __half22float2(__ldcs((const __half2*)(wp + 2 * lane)));
        float2 WB = __half22float2(__ldcs((const __half2*)(wp + 64 + 2 * lane)));
        float2 WC = __half22float2(__ldcs((const __half2*)(wp + 128 + 2 * lane)));
        float2 WD = __half22float2(__ldcs((const __half2*)(wp + 192 + 2 * lane)));

        {
            float g1x = Ga.x, g1y = Ga.y, g1z = Gb.x;
            float d3 = fmaf(g1x, y1x, fmaf(g1y, y1y, g1z * y1z));
            sa0 = fmaf(WA.x * G0.x, y0, sa0);
            sb0 = fmaf(WB.x, d3, sb0);
            float cg = WC.x * G0.x;
            va0x = fmaf(cg, y1x, va0x); va0y = fmaf(cg, y1y, va0y); va0z = fmaf(cg, y1z, va0z);
            float dg = WD.x * y0;
            vb0x = fmaf(dg, g1x, vb0x); vb0y = fmaf(dg, g1y, vb0y); vb0z = fmaf(dg, g1z, vb0z);
        }
        {
            float g1x = Gb.y, g1y = Gc.x, g1z = Gc.y;
            float d3 = fmaf(g1x, y1x, fmaf(g1y, y1y, g1z * y1z));
            sa1 = fmaf(WA.y * G0.y, y0, sa1);
            sb1 = fmaf(WB.y, d3, sb1);
            float cg = WC.y * G0.y;
            va1x = fmaf(cg, y1x, va1x); va1y = fmaf(cg, y1y, va1y); va1z = fmaf(cg, y1z, va1z);
            float dg = WD.y * y0;
            vb1x = fmaf(dg, g1x, vb1x); vb1y = fmaf(dg, g1y, vb1y); vb1z = fmaf(dg, g1z, vb1z);
        }
    }

    float a = attr[n];
    float scale = a * rsqrtf(deg[n]) * INV_SQRT128;
    float scb   = scale * INV_SQRT3;
    float4* sv = (float4*)(s_sv + w * 512);
    sv[2 * lane]      = make_float4(sa0 * scale, va0x * scale, va0y * scale, va0z * scale);
    sv[2 * lane + 1]  = make_float4(sa1 * scale, va1x * scale, va1y * scale, va1z * scale);
    sv[64 + 2 * lane]     = make_float4(sb0 * scb, vb0x * scale, vb0y * scale, vb0z * scale);
    sv[64 + 2 * lane + 1] = make_float4(sb1 * scb, vb1x * scale, vb1y * scale, vb1z * scale);
    __syncwarp();

    float o0a = 0.f, o0b = 0.f;
    float o1ax=0.f,o1ay=0.f,o1az=0.f, o1bx=0.f,o1by=0.f,o1bz=0.f;
#pragma unroll 4
    for (int u = 0; u < 128; u++) {
        float4 svu = sv[u];
        float2 w0 = *(const float2*)(sW0 + u * 64 + 2 * lane);
        float2 w1 = *(const float2*)(sW1 + u * 64 + 2 * lane);
        o0a = fmaf(svu.x, w0.x, o0a);
        o0b = fmaf(svu.x, w0.y, o0b);
        o1ax = fmaf(svu.y, w1.x, o1ax); o1ay = fmaf(svu.z, w1.x, o1ay); o1az = fmaf(svu.w, w1.x, o1az);
        o1bx = fmaf(svu.y, w1.y, o1bx); o1by = fmaf(svu.z, w1.y, o1by); o1bz = fmaf(svu.w, w1.y, o1bz);
    }

    float* op = out + n * 256;
    int k0 = 2 * lane;
    op[k0]     += C_X * o0a;
    op[k0 + 1] += C_X * o0b;
    int b0 = 64 + 3 * k0;
    op[b0 + 0] += C_X * o1ax; op[b0 + 1] += C_X * o1ay; op[b0 + 2] += C_X * o1az;
    op[b0 + 3] += C_X * o1bx; op[b0 + 4] += C_X * o1by; op[b0 + 5] += C_X * o1bz;
}

// ============================================================================
extern "C" void kernel_launch(void* const* d_in, const int* in_sizes, int n_in,
                              void* d_out, int out_size)
{
    const float* node_input = (const float*)d_in[0];
    const float* node_attr  = (const float*)d_in[1];
    const float* node_deg   = (const float*)d_in[2];
    const float* edge_attr  = (const float*)d_in[3];
    const float* elen       = (const float*)d_in[4];
    const float* W_li0      = (const float*)d_in[5];
    const float* W_li1      = (const float*)d_in[6];
    const float* W_lm0      = (const float*)d_in[7];
    const float* W_lm1      = (const float*)d_in[8];
    const float* W_mlp1     = (const float*)d_in[9];
    const float* W_mlp2     = (const float*)d_in[10];
    const float* W_lo0      = (const float*)d_in[11];
    const float* W_lo1      = (const float*)d_in[12];
    const int*   edge_src   = (const int*)d_in[13];
    const int*   edge_dst   = (const int*)d_in[14];
    float* out = (float*)d_out;

    static int attr_set = 0;
    if (!attr_set) {
        cudaFuncSetAttribute(k_node, cudaFuncAttributeMaxDynamicSharedMemorySize, 73760);
        cudaFuncSetAttribute(k_pull, cudaFuncAttributeMaxDynamicSharedMemorySize, 81920);
        cudaFuncSetAttribute(k_mlp_mma, cudaFuncAttributeMaxDynamicSharedMemorySize, MLP_SMEM);
        attr_set = 1;
    }

    // order keeps k_mlp_mma in the ncu-captured slot (#4)
    k_zero<<<(N_NODES + 255) / 256, 256>>>();
    k_hist<<<N_EDGES / 256, 256>>>(edge_dst);
    k_prep<<<120, 256>>>(W_mlp2, W_mlp1);
    k_mlp_mma<<<(N_EDGES / 128) * 2, 256, MLP_SMEM>>>(elen);
    k_scan<<<1, 1024>>>();
    k_fill<<<N_EDGES / 256, 256>>>(edge_dst, edge_src, edge_attr);
    k_node<<<N_NODES / 8, 256, 73760>>>(node_input, node_attr, node_deg,
                                        W_li0, W_li1, W_lm0, W_lm1, out);
    k_pull<<<N_NODES / 8, 256, 81920>>>(node_attr, node_deg,
                                        W_lo0, W_lo1, out);
}

// round 11
// speedup vs baseline: 1.3352x; 1.0093x over previous
#include <cuda_runtime.h>
#include <cuda_fp16.h>
#include <cstdint>

#define N_NODES 20000
#define N_EDGES 320000

// ---------------- device scratch ------------------------------------------
__device__ float  g_f [N_NODES * 256];      // f0|f1 (deg/attr/inv8 folded in)
__device__ __half g_ewh[N_EDGES * 256];     // per-edge MLP weights, EDGE-ORDER, fp16
__device__ int    g_cnt[N_NODES];
__device__ int    g_off[N_NODES + 1];
__device__ int    g_cur[N_NODES];
__device__ int    g_eid[N_EDGES];           // sorted position -> edge id
__device__ int    g_srcp[N_EDGES];          // sorted position -> src node
__device__ float4 g_eap[N_EDGES];           // sorted position -> edge_attr
__device__ __half g_W2t_h[256 * 112];       // W2^T fp16 hi, [n][k]
__device__ __half g_W2t_l[256 * 112];       // W2^T fp16 lo
__device__ __half g_W1t_h[112 * 16];        // W1^T fp16 hi
__device__ __half g_W1t_l[112 * 16];        // W1^T fp16 lo

// ---------------- constants -----------------------------------------------
#define INV8        0.125f
#define INV_SQRT10  0.3162277660168379f
#define INV10       0.1f
#define INV_SQRT3   0.5773502691896258f
#define INV_SQRT128 0.08838834764831845f
#define C_S         0.3826834323650898f
#define C_X         0.9238795325112867f

// ============================================================================
// K1: node self-interaction (unchanged)
// ============================================================================
__global__ __launch_bounds__(256) void k_node(
    const float* __restrict__ x, const float* __restrict__ attr,
    const float* __restrict__ deg,
    const float* __restrict__ Wli0, const float* __restrict__ Wli1,
    const float* __restrict__ Wlm0, const float* __restrict__ Wlm1,
    float* __restrict__ out)
{
    extern __shared__ float sm[];
    float* sWf0 = sm;
    float* sWf1 = sm + 4096;
    float* sWm0 = sm + 8192;
    float* sWm1 = sm + 12288;
    float* sx   = sm + 16384;     // 8 * 257

    int t = threadIdx.x;
    for (int i = t; i < 4096; i += 256) {
        sWf0[i] = Wli0[i]; sWf1[i] = Wli1[i];
        sWm0[i] = Wlm0[i]; sWm1[i] = Wlm1[i];
    }
    int nb = blockIdx.x * 8;
    for (int i = t; i < 8 * 256; i += 256) {
        int node = i >> 8, cc = i & 255;
        sx[node * 257 + cc] = x[(nb + node) * 256 + cc];
    }
    __syncthreads();

    int c = t;
    bool isS = (c < 64);
    int k = isS ? c : (c - 64) / 3;
    int m = isS ? 0 : (c - 64) % 3;
    int xoff = isS ? 0 : (64 + m);
    int xstr = isS ? 1 : 3;
    const float* wf = (isS ? sWf0 : sWf1) + k;
    const float* wm = (isS ? sWm0 : sWm1) + k;
    const float* xp = sx + xoff;

    float accf[8], accm[8];
#pragma unroll
    for (int i = 0; i < 8; i++) { accf[i] = 0.f; accm[i] = 0.f; }

#pragma unroll 4
    for (int u = 0; u < 64; u++) {
        float vf = wf[u * 64];
        float vm = wm[u * 64];
#pragma unroll
        for (int i = 0; i < 8; i++) {
            float xv = xp[i * 257 + u * xstr];
            accf[i] = fmaf(xv, vf, accf[i]);
            accm[i] = fmaf(xv, vm, accm[i]);
        }
    }
#pragma unroll
    for (int i = 0; i < 8; i++) {
        int n = nb + i;
        float a  = attr[n];
        float sf = INV8 * a * rsqrtf(deg[n]);
        float sc = INV8 * a * C_S;
        g_f[n * 256 + c] = accf[i] * sf;
        out[n * 256 + c] = accm[i] * sc;
    }
}

// ============================================================================
// CSR build kernels (unchanged)
// ============================================================================
__global__ __launch_bounds__(256) void k_zero() {
    int i = blockIdx.x * 256 + threadIdx.x;
    if (i < N_NODES) g_cnt[i] = 0;
}
__global__ __launch_bounds__(256) void k_hist(const int* __restrict__ dst) {
    int i = blockIdx.x * 256 + threadIdx.x;
    if (i < N_EDGES) atomicAdd(&g_cnt[dst[i]], 1);
}
__global__ __launch_bounds__(1024) void k_scan() {
    int t = threadIdx.x, lane = t & 31, wid = t >> 5;
    __shared__ int wsum[32];
    int base = t * 20;
    int loc[20];
    int s = 0;
#pragma unroll
    for (int j = 0; j < 20; j++) {
        int i = base + j;
        int v = (i < N_NODES) ? g_cnt[i] : 0;
        loc[j] = s; s += v;
    }
    int x = s;
#pragma unroll
    for (int d = 1; d < 32; d <<= 1) {
        int y = __shfl_up_sync(0xffffffffu, x, d);
        if (lane >= d) x += y;
    }
    if (lane == 31) wsum[wid] = x;
    __syncthreads();
    if (wid == 0) {
        int v2 = wsum[lane];
#pragma unroll
        for (int d = 1; d < 32; d <<= 1) {
            int y = __shfl_up_sync(0xffffffffu, v2, d);
            if (lane >= d) v2 += y;
        }
        wsum[lane] = v2;
    }
    __syncthreads();
    int excl = (wid ? wsum[wid - 1] : 0) + x - s;
#pragma unroll
    for (int j = 0; j < 20; j++) {
        int i = base + j;
        if (i < N_NODES) { g_off[i] = excl + loc[j]; g_cur[i] = excl + loc[j]; }
    }
    if (t == 1023) g_off[N_NODES] = excl + s;
}
__global__ __launch_bounds__(256) void k_fill(
    const int* __restrict__ dst, const int* __restrict__ src,
    const float* __restrict__ eattr)
{
    int i = blockIdx.x * 256 + threadIdx.x;
    if (i < N_EDGES) {
        int d = dst[i];
        int p = atomicAdd(&g_cur[d], 1);
        g_eid[p]  = i;
        g_srcp[p] = src[i];
        g_eap[p]  = ((const float4*)eattr)[i];
    }
}

// ============================================================================
// K-prep: W2^T fp16 hi/lo [256][112]  +  W1^T fp16 hi/lo [112][16]
// ============================================================================
__global__ __launch_bounds__(256) void k_prep(
    const float* __restrict__ W2, const float* __restrict__ W1)
{
    int idx = blockIdx.x * 256 + threadIdx.x;
    if (idx < 256 * 112) {
        int n = idx / 112, k = idx - n * 112;
        float v = (k < 100) ? W2[k * 256 + n] : 0.0f;
        __half h = __float2half_rn(v);
        g_W2t_h[idx] = h;
        g_W2t_l[idx] = __float2half_rn(v - __half2float(h));
    }
    int j = idx - 256 * 112;
    if (j >= 0 && j < 112 * 16) {
        int n = j >> 4, k = j & 15;
        float v = (k < 10 && n < 100) ? W1[k * 100 + n] : 0.0f;
        __half h = __float2half_rn(v);
        g_W1t_h[j] = h;
        g_W1t_l[j] = __float2half_rn(v - __half2float(h));
    }
}

// ============================================================================
// K2 (unchanged from R10): layer-1 HMMA + R8-shape mainloop
// ============================================================================
#define RSTR 120
#define ESTR 24
#define OFF_A   0
#define OFF_ELH 0
#define OFF_ELL 6144
#define OFF_W1H 12288
#define OFF_W1L 17664
#define OFF_BH  30720
#define OFF_BL  61440
#define MLP_SMEM 92160

__device__ __forceinline__ uint32_t smem_u32(const void* p) {
    uint32_t a;
    asm("{ .reg .u64 t; cvta.to.shared.u64 t, %1; cvt.u32.u64 %0, t; }"
        : "=r"(a) : "l"(p));
    return a;
}
#define LDMX4(r, addr) \
    asm volatile("ldmatrix.sync.aligned.m8n8.x4.shared.b16 {%0,%1,%2,%3}, [%4];" \
        : "=r"((r)[0]), "=r"((r)[1]), "=r"((r)[2]), "=r"((r)[3]) \
        : "r"(addr))

__device__ __forceinline__ void mma16816h(
    float& c0, float& c1, float& c2, float& c3,
    uint32_t a0, uint32_t a1, uint32_t a2, uint32_t a3,
    uint32_t b0, uint32_t b1)
{
    asm volatile(
        "mma.sync.aligned.m16n8k16.row.col.f32.f16.f16.f32 "
        "{%0,%1,%2,%3}, {%4,%5,%6,%7}, {%8,%9}, {%0,%1,%2,%3};"
        : "+f"(c0), "+f"(c1), "+f"(c2), "+f"(c3)
        : "r"(a0), "r"(a1), "r"(a2), "r"(a3), "r"(b0), "r"(b1));
}

__device__ __forceinline__ float silu_f(float x) {
    return x / (1.0f + __expf(-x));
}

__global__ __launch_bounds__(256, 2) void k_mlp_mma(
    const float* __restrict__ elen)
{
    extern __shared__ char smc[];
    __half* sA = (__half*)(smc + OFF_A);

    int t = threadIdx.x, wid = t >> 5, lane = t & 31;
    int e0 = (blockIdx.x >> 1) * 128;
    int nb = (blockIdx.x & 1) * 128;

    if (t < 128) {
        const float* ep = elen + (size_t)(e0 + t) * 10;
        __half* dh = (__half*)(smc + OFF_ELH) + t * ESTR;
        __half* dl = (__half*)(smc + OFF_ELL) + t * ESTR;
#pragma unroll
        for (int b = 0; b < 10; b++) {
            float v = __ldg(ep + b);
            __half h = __float2half_rn(v);
            dh[b] = h;
            dl[b] = __float2half_rn(v - __half2float(h));
        }
#pragma unroll
        for (int b = 10; b < 16; b++) { dh[b] = __half(0.f); dl[b] = __half(0.f); }
    } else {
        int r = t - 128;
        if (r < 112) {
            const uint4* srcH = (const uint4*)(g_W1t_h + r * 16);
            const uint4* srcL = (const uint4*)(g_W1t_l + r * 16);
            uint4* dstH = (uint4*)((__half*)(smc + OFF_W1H) + r * ESTR);
            uint4* dstL = (uint4*)((__half*)(smc + OFF_W1L) + r * ESTR);
            dstH[0] = srcH[0]; dstH[1] = srcH[1];
            dstL[0] = srcL[0]; dstL[1] = srcL[1];
        }
    }
    {
        int n_local = t >> 1, half = t & 1;
        int goff = (nb + n_local) * 112 + half * 56;
        const uint4* srcH = (const uint4*)(g_W2t_h + goff);
        const uint4* srcL = (const uint4*)(g_W2t_l + goff);
        uint4* dstH = (uint4*)(smc + OFF_BH + n_local * RSTR * 2 + half * 112);
        uint4* dstL = (uint4*)(smc + OFF_BL + n_local * RSTR * 2 + half * 112);
#pragma unroll
        for (int j = 0; j < 7; j++) { dstH[j] = srcH[j]; dstL[j] = srcL[j]; }
    }
    __syncthreads();

    uint32_t sb = smem_u32(smc);

    float hacc[14][4];
#pragma unroll
    for (int nt = 0; nt < 14; nt++)
#pragma unroll
        for (int j = 0; j < 4; j++) hacc[nt][j] = 0.f;
    {
        uint32_t aoff = (((16 * wid + (lane & 15)) * ESTR + (lane >> 4) * 8) << 1);
        uint32_t boff = ((((lane & 7) + (lane >> 4) * 8) * ESTR
                          + ((lane >> 3) & 1) * 8) << 1);
        uint32_t ah[4], al[4];
        LDMX4(ah, sb + OFF_ELH + aoff);
        LDMX4(al, sb + OFF_ELL + aoff);
#pragma unroll
        for (int p2 = 0; p2 < 7; p2++) {
            uint32_t bstep = p2 * (16 * ESTR * 2);
            uint32_t bh[4], bl[4];
            LDMX4(bh, sb + OFF_W1H + boff + bstep);
            LDMX4(bl, sb + OFF_W1L + boff + bstep);
            int n0 = 2 * p2, n1 = 2 * p2 + 1;
            mma16816h(hacc[n0][0], hacc[n0][1], hacc[n0][2], hacc[n0][3],
                      ah[0], ah[1], ah[2], ah[3], bh[0], bh[1]);
            mma16816h(hacc[n1][0], hacc[n1][1], hacc[n1][2], hacc[n1][3],
                      ah[0], ah[1], ah[2], ah[3], bh[2], bh[3]);
            mma16816h(hacc[n0][0], hacc[n0][1], hacc[n0][2], hacc[n0][3],
                      ah[0], ah[1], ah[2], ah[3], bl[0], bl[1]);
            mma16816h(hacc[n1][0], hacc[n1][1], hacc[n1][2], hacc[n1][3],
                      ah[0], ah[1], ah[2], ah[3], bl[2], bl[3]);
            mma16816h(hacc[n0][0], hacc[n0][1], hacc[n0][2], hacc[n0][3],
                      al[0], al[1], al[2], al[3], bh[0], bh[1]);
            mma16816h(hacc[n1][0], hacc[n1][1], hacc[n1][2], hacc[n1][3],
                      al[0], al[1], al[2], al[3], bh[2], bh[3]);
        }
    }
    __syncthreads();

    {
        int row = 16 * wid + (lane >> 2);
#pragma unroll
        for (int nt = 0; nt < 14; nt++) {
            int col = nt * 8 + (lane & 3) * 2;
            float x0 = hacc[nt][0] * INV_SQRT10;
            float x1 = hacc[nt][1] * INV_SQRT10;
            float x2 = hacc[nt][2] * INV_SQRT10;
            float x3 = hacc[nt][3] * INV_SQRT10;
            *(__half2*)(sA + row * RSTR + col) =
                __floats2half2_rn(silu_f(x0), silu_f(x1));
            *(__half2*)(sA + (row + 8) * RSTR + col) =
                __floats2half2_rn(silu_f(x2), silu_f(x3));
        }
    }
    __syncthreads();

    int wm = wid & 3;
    int wn = wid >> 2;

    uint32_t aAddr = sb + OFF_A +
        (((32 * wm + (lane & 15)) * RSTR + (lane >> 4) * 8) << 1);
    uint32_t bOff = (((64 * wn + (lane & 7) + (lane >> 4) * 8) * RSTR
                      + ((lane >> 3) & 1) * 8) << 1);
    uint32_t bAddrH = sb + OFF_BH + bOff;
    uint32_t bAddrL = sb + OFF_BL + bOff;

    float acc[2][8][4];
#pragma unroll
    for (int mt = 0; mt < 2; mt++)
#pragma unroll
        for (int nt = 0; nt < 8; nt++)
#pragma unroll
            for (int j = 0; j < 4; j++) acc[mt][nt][j] = 0.f;

#pragma unroll 1
    for (int ks = 0; ks < 7; ks++) {
        uint32_t kb = ks * 32;
        uint32_t a[2][4];
        LDMX4(a[0], aAddr + kb);
        LDMX4(a[1], aAddr + 16 * RSTR * 2 + kb);
#pragma unroll
        for (int pass = 0; pass < 2; pass++) {
            uint32_t base = (pass ? bAddrL : bAddrH) + kb;
#pragma unroll
            for (int j = 0; j < 4; j++) {
                uint32_t b[4];
                LDMX4(b, base + j * (16 * RSTR * 2));
#pragma unroll
                for (int mt = 0; mt < 2; mt++) {
                    mma16816h(acc[mt][2*j][0], acc[mt][2*j][1],
                              acc[mt][2*j][2], acc[mt][2*j][3],
                              a[mt][0], a[mt][1], a[mt][2], a[mt][3],
                              b[0], b[1]);
                    mma16816h(acc[mt][2*j+1][0], acc[mt][2*j+1][1],
                              acc[mt][2*j+1][2], acc[mt][2*j+1][3],
                              a[mt][0], a[mt][1], a[mt][2], a[mt][3],
                              b[2], b[3]);
                }
            }
        }
    }

    int erow = e0 + 32 * wm + (lane >> 2);
    int col  = nb + 64 * wn + (lane & 3) * 2;
#pragma unroll
    for (int mt = 0; mt < 2; mt++) {
        __half* r0 = g_ewh + (size_t)(erow + mt * 16) * 256 + col;
        __half* r1 = r0 + 8 * 256;
#pragma unroll
        for (int nt = 0; nt < 8; nt++) {
            int c = nt * 8;
            __stcs((__half2*)(r0 + c),
                   __floats2half2_rn(acc[mt][nt][0] * INV10, acc[mt][nt][1] * INV10));
            __stcs((__half2*)(r1 + c),
                   __floats2half2_rn(acc[mt][nt][2] * INV10, acc[mt][nt][3] * INV10));
        }
    }
}

// ============================================================================
// K3: pull kernel — explicit 1-deep software pipeline (loads for edge p+1
// issued while computing edge p; src/eid indices run 2 ahead). Arithmetic
// order per output element is IDENTICAL to R10.
// ============================================================================
__global__ __launch_bounds__(256) void k_pull(
    const float* __restrict__ attr, const float* __restrict__ deg,
    const float* __restrict__ Wlo0, const float* __restrict__ Wlo1,
    float* __restrict__ out)
{
    extern __shared__ float sm[];
    float* sW0  = sm;
    float* sW1  = sm + 8192;
    float* s_sv = sm + 16384;

    int t = threadIdx.x;
    for (int i = t; i < 8192; i += 256) { sW0[i] = Wlo0[i]; sW1[i] = Wlo1[i]; }
    __syncthreads();

    int w = t >> 5, lane = t & 31;
    int n = blockIdx.x * 8 + w;
    int beg = g_off[n], end = g_off[n + 1];

    float sa0 = 0.f, sa1 = 0.f, sb0 = 0.f, sb1 = 0.f;
    float va0x=0.f,va0y=0.f,va0z=0.f, va1x=0.f,va1y=0.f,va1z=0.f;
    float vb0x=0.f,vb0y=0.f,vb0z=0.f, vb1x=0.f,vb1y=0.f,vb1z=0.f;

    // index pipeline (2 ahead)
    int srcB = (beg + 1 < end) ? __ldg(&g_srcp[beg + 1]) : 0;
    int eidB = (beg + 1 < end) ? __ldg(&g_eid[beg + 1])  : 0;

    // data pipeline: current-edge registers
    float4  eaC = make_float4(0.f, 0.f, 0.f, 0.f);
    float2  G0C = make_float2(0.f, 0.f), GaC = G0C, GbC = G0C, GcC = G0C;
    __half2 WAC = __floats2half2_rn(0.f, 0.f), WBC = WAC, WCC = WAC, WDC = WAC;

    if (beg < end) {
        int srcA = __ldg(&g_srcp[beg]);
        int eidA = __ldg(&g_eid[beg]);
        const float*  fp = g_f   + srcA * 256;
        const __half* wp = g_ewh + (size_t)eidA * 256;
        eaC = __ldg(&g_eap[beg]);
        G0C = *(const float2*)(fp + 2 * lane);
        GaC = *(const float2*)(fp + 64 + 6 * lane);
        GbC = *(const float2*)(fp + 64 + 6 * lane + 2);
        GcC = *(const float2*)(fp + 64 + 6 * lane + 4);
        WAC = __ldcs((const __half2*)(wp + 2 * lane));
        WBC = __ldcs((const __half2*)(wp + 64 + 2 * lane));
        WCC = __ldcs((const __half2*)(wp + 128 + 2 * lane));
        WDC = __ldcs((const __half2*)(wp + 192 + 2 * lane));
    }

    for (int p = beg; p < end; p++) {
        // issue loads for edge p+1 (data) and p+2 (indices) FIRST
        int srcN = (p + 2 < end) ? __ldg(&g_srcp[p + 2]) : 0;
        int eidN = (p + 2 < end) ? __ldg(&g_eid[p + 2])  : 0;
        float4  eaN = make_float4(0.f, 0.f, 0.f, 0.f);
        float2  G0N = make_float2(0.f, 0.f), GaN = G0N, GbN = G0N, GcN = G0N;
        __half2 WAN = __floats2half2_rn(0.f, 0.f), WBN = WAN, WCN = WAN, WDN = WAN;
        if (p + 1 < end) {
            const float*  fp = g_f   + srcB * 256;
            const __half* wp = g_ewh + (size_t)eidB * 256;
            eaN = __ldg(&g_eap[p + 1]);
            G0N = *(const float2*)(fp + 2 * lane);
            GaN = *(const float2*)(fp + 64 + 6 * lane);
            GbN = *(const float2*)(fp + 64 + 6 * lane + 2);
            GcN = *(const float2*)(fp + 64 + 6 * lane + 4);
            WAN = __ldcs((const __half2*)(wp + 2 * lane));
            WBN = __ldcs((const __half2*)(wp + 64 + 2 * lane));
            WCN = __ldcs((const __half2*)(wp + 128 + 2 * lane));
            WDN = __ldcs((const __half2*)(wp + 192 + 2 * lane));
        }

        // compute edge p from current registers (identical math to R10)
        float y0 = eaC.x, y1x = eaC.y, y1y = eaC.z, y1z = eaC.w;
        float2 WA = __half22float2(WAC);
        float2 WB = __half22float2(WBC);
        float2 WC = __half22float2(WCC);
        float2 WD = __half22float2(WDC);
        {
            float g1x = GaC.x, g1y = GaC.y, g1z = GbC.x;
            float d3 = fmaf(g1x, y1x, fmaf(g1y, y1y, g1z * y1z));
            sa0 = fmaf(WA.x * G0C.x, y0, sa0);
            sb0 = fmaf(WB.x, d3, sb0);
            float cg = WC.x * G0C.x;
            va0x = fmaf(cg, y1x, va0x); va0y = fmaf(cg, y1y, va0y); va0z = fmaf(cg, y1z, va0z);
            float dg = WD.x * y0;
            vb0x = fmaf(dg, g1x, vb0x); vb0y = fmaf(dg, g1y, vb0y); vb0z = fmaf(dg, g1z, vb0z);
        }
        {
            float g1x = GbC.y, g1y = GcC.x, g1z = GcC.y;
            float d3 = fmaf(g1x, y1x, fmaf(g1y, y1y, g1z * y1z));
            sa1 = fmaf(WA.y * G0C.y, y0, sa1);
            sb1 = fmaf(WB.y, d3, sb1);
            float cg = WC.y * G0C.y;
            va1x = fmaf(cg, y1x, va1x); va1y = fmaf(cg, y1y, va1y); va1z = fmaf(cg, y1z, va1z);
            float dg = WD.y * y0;
            vb1x = fmaf(dg, g1x, vb1x); vb1y = fmaf(dg, g1y, vb1y); vb1z = fmaf(dg, g1z, vb1z);
        }

        // rotate pipeline
        eaC = eaN; G0C = G0N; GaC = GaN; GbC = GbN; GcC = GcN;
        WAC = WAN; WBC = WBN; WCC = WCN; WDC = WDN;
        srcB = srcN; eidB = eidN;
    }

    float a = attr[n];
    float scale = a * rsqrtf(deg[n]) * INV_SQRT128;
    float scb   = scale * INV_SQRT3;
    float4* sv = (float4*)(s_sv + w * 512);
    sv[2 * lane]      = make_float4(sa0 * scale, va0x * scale, va0y * scale, va0z * scale);
    sv[2 * lane + 1]  = make_float4(sa1 * scale, va1x * scale, va1y * scale, va1z * scale);
    sv[64 + 2 * lane]     = make_float4(sb0 * scb, vb0x * scale, vb0y * scale, vb0z * scale);
    sv[64 + 2 * lane + 1] = make_float4(sb1 * scb, vb1x * scale, vb1y * scale, vb1z * scale);
    __syncwarp();

    float o0a = 0.f, o0b = 0.f;
    float o1ax=0.f,o1ay=0.f,o1az=0.f, o1bx=0.f,o1by=0.f,o1bz=0.f;
#pragma unroll 4
    for (int u = 0; u < 128; u++) {
        float4 svu = sv[u];
        float2 w0 = *(const float2*)(sW0 + u * 64 + 2 * lane);
        float2 w1 = *(const float2*)(sW1 + u * 64 + 2 * lane);
        o0a = fmaf(svu.x, w0.x, o0a);
        o0b = fmaf(svu.x, w0.y, o0b);
        o1ax = fmaf(svu.y, w1.x, o1ax); o1ay = fmaf(svu.z, w1.x, o1ay); o1az = fmaf(svu.w, w1.x, o1az);
        o1bx = fmaf(svu.y, w1.y, o1bx); o1by = fmaf(svu.z, w1.y, o1by); o1bz = fmaf(svu.w, w1.y, o1bz);
    }

    float* op = out + n * 256;
    int k0 = 2 * lane;
    op[k0]     += C_X * o0a;
    op[k0 + 1] += C_X * o0b;
    int b0 = 64 + 3 * k0;
    op[b0 + 0] += C_X * o1ax; op[b0 + 1] += C_X * o1ay; op[b0 + 2] += C_X * o1az;
    op[b0 + 3] += C_X * o1bx; op[b0 + 4] += C_X * o1by; op[b0 + 5] += C_X * o1bz;
}

// ============================================================================
extern "C" void kernel_launch(void* const* d_in, const int* in_sizes, int n_in,
                              void* d_out, int out_size)
{
    const float* node_input = (const float*)d_in[0];
    const float* node_attr  = (const float*)d_in[1];
    const float* node_deg   = (const float*)d_in[2];
    const float* edge_attr  = (const float*)d_in[3];
    const float* elen       = (const float*)d_in[4];
    const float* W_li0      = (const float*)d_in[5];
    const float* W_li1      = (const float*)d_in[6];
    const float* W_lm0      = (const float*)d_in[7];
    const float* W_lm1      = (const float*)d_in[8];
    const float* W_mlp1     = (const float*)d_in[9];
    const float* W_mlp2     = (const float*)d_in[10];
    const float* W_lo0      = (const float*)d_in[11];
    const float* W_lo1      = (const float*)d_in[12];
    const int*   edge_src   = (const int*)d_in[13];
    const int*   edge_dst   = (const int*)d_in[14];
    float* out = (float*)d_out;

    static int attr_set = 0;
    if (!attr_set) {
        cudaFuncSetAttribute(k_node, cudaFuncAttributeMaxDynamicSharedMemorySize, 73760);
        cudaFuncSetAttribute(k_pull, cudaFuncAttributeMaxDynamicSharedMemorySize, 81920);
        cudaFuncSetAttribute(k_mlp_mma, cudaFuncAttributeMaxDynamicSharedMemorySize, MLP_SMEM);
        attr_set = 1;
    }

    // order keeps k_mlp_mma in the ncu-captured slot (#4)
    k_zero<<<(N_NODES + 255) / 256, 256>>>();
    k_hist<<<N_EDGES / 256, 256>>>(edge_dst);
    k_prep<<<120, 256>>>(W_mlp2, W_mlp1);
    k_mlp_mma<<<(N_EDGES / 128) * 2, 256, MLP_SMEM>>>(elen);
    k_scan<<<1, 1024>>>();
    k_fill<<<N_EDGES / 256, 256>>>(edge_dst, edge_src, edge_attr);
    k_node<<<N_NODES / 8, 256, 73760>>>(node_input, node_attr, node_deg,
                                        W_li0, W_li1, W_lm0, W_lm1, out);
    k_pull<<<N_NODES / 8, 256, 81920>>>(node_attr, node_deg,
                                        W_lo0, W_lo1, out);
}